// round 14
// baseline (speedup 1.0000x reference)
#include <cuda_runtime.h>
#include <cuda_fp16.h>
#include <cstdint>
#include <cstddef>

// Problem constants
#define SEQ   2048
#define BATCH 2
#define TOK   (SEQ * BATCH)   // 4096
#define DM    2048
#define NH    32
#define NKV   8
#define HD    64
#define KVD   (NKV * HD)      // 512

// ------------------------------------------------------------------
// Scratch (device globals; no cudaMalloc allowed)
// ------------------------------------------------------------------
__device__ float g_q[(size_t)TOK * DM];
__device__ float g_k[(size_t)TOK * KVD];
__device__ float g_v[(size_t)TOK * KVD];
__device__ float g_attn[(size_t)TOK * DM];

// Exact fp32 rounding of 10000^(-i/32), i = 0..31
__device__ __constant__ float c_invfreq[32] = {
    1.0f, 0.7498942093324559f, 0.5623413251903491f, 0.4216965034285822f,
    0.31622776601683794f, 0.23713737056616552f, 0.17782794100389228f, 0.1333521432163324f,
    0.1f, 0.07498942093324559f, 0.05623413251903491f, 0.04216965034285822f,
    0.031622776601683794f, 0.023713737056616552f, 0.017782794100389228f, 0.01333521432163324f,
    0.01f, 0.007498942093324559f, 0.005623413251903491f, 0.004216965034285822f,
    0.0031622776601683794f, 0.0023713737056616552f, 0.0017782794100389228f, 0.001333521432163324f,
    0.001f, 0.0007498942093324559f, 0.0005623413251903491f, 0.0004216965034285822f,
    0.00031622776601683794f, 0.00023713737056616552f, 0.00017782794100389228f, 0.0001333521432163324f
};

// ------------------------------------------------------------------
// fp16 helpers (baseline PTX, works on compute_103 virtual arch)
// ------------------------------------------------------------------
__device__ __forceinline__ uint32_t pack_h2(float lo, float hi) {
    __half2 h = __floats2half2_rn(lo, hi);
    return *reinterpret_cast<uint32_t*>(&h);
}
__device__ __forceinline__ float ex2f(float x) {
    float r;
    asm("ex2.approx.f32 %0, %1;" : "=f"(r) : "f"(x));
    return r;
}
__device__ __forceinline__ void mma_f16(float c[4], const uint32_t a[4], const uint32_t b[2]) {
    asm volatile("mma.sync.aligned.m16n8k16.row.col.f32.f16.f16.f32 "
                 "{%0,%1,%2,%3}, {%4,%5,%6,%7}, {%8,%9}, {%0,%1,%2,%3};"
                 : "+f"(c[0]), "+f"(c[1]), "+f"(c[2]), "+f"(c[3])
                 : "r"(a[0]), "r"(a[1]), "r"(a[2]), "r"(a[3]), "r"(b[0]), "r"(b[1]));
}

// Weight scale 2^6 (exact) to avoid fp16 subnormals; descale in epilogue.
#define WSCALE 64.0f
#define WDESC  0.015625f

// word-index permutation within 8-groups: pos(w) = [0,4,1,5,2,6,3,7]
// so fragment pairs (w, w+4) become adjacent -> LDS.64.
__device__ __forceinline__ int wperm(int w) {
    int lo = w & 7;
    return (w & ~7) | ((lo < 4) ? (lo << 1) : (((lo - 4) << 1) | 1));
}

// ==================================================================
// fp16 mma.sync GEMM core, round 14:
// CTA tile 128x128, K-chunk 32, 256 threads = 8 warps (2m x 4n),
// warp tile 64x32. TWO CTAs co-resident per SM (independent sync
// domains overlap chunk-boundary bubbles).
// A smem: [128][20] f16x2 words, k-pair PERMUTED -> af via LDS.64.
// B smem packed k-pairs: [16][136] words (word j,n = (B[2j][n],B[2j+1][n]))
// ==================================================================
#define GBM 128
#define GBN 128
#define GBK 32
#define AS_U32 (128 * 20)   // 2560 words
#define BS_U32 (16 * 136)   // 2176 words
#define GEMM_SMEM_BYTES ((AS_U32 + BS_U32) * 2 * 4)  // 37888

template <int ROPE_MODE>
__device__ __forceinline__ void gemm_core(
    const float* __restrict__ A, const float* __restrict__ B,
    float* __restrict__ C, int N, int K, int m0, int n0,
    const int* __restrict__ pos, uint32_t* smu)
{
    uint32_t* As = smu;                 // 2 buffers
    uint32_t* Bs = smu + 2 * AS_U32;

    const int tid = threadIdx.x;
    const int wid = tid >> 5, lane = tid & 31;
    const int g = lane >> 2, q = lane & 3;
    const int warp_m = wid >> 2;           // 0..1 (64 rows)
    const int warp_n = wid & 3;            // 0..3 (32 cols)

    // loaders (256 threads):
    // A tile 128x32: arow = tid>>3 (0..31), 4 row-groups of 32; 1 float4 each.
    // B tile 32x128 as 16 k-pair rows: bj = tid>>5 (0..7), pairs {bj, bj+8}.
    const int arow = tid >> 3;
    const int acol4 = (tid & 7) * 4;
    const int aj = (tid & 7) * 2;          // original word indices aj, aj+1
    const int ap0 = wperm(aj), ap1 = wperm(aj + 1);
    const int bj = tid >> 5;
    const int bcol4 = (tid & 31) * 4;
    const float* Ag = A + (size_t)(m0 + arow) * K + acol4;
    const float* Bg = B + (size_t)(2 * bj) * N + n0 + bcol4;

    float acc[4][4][4];
#pragma unroll
    for (int mt = 0; mt < 4; mt++)
#pragma unroll
        for (int nt = 0; nt < 4; nt++)
#pragma unroll
            for (int e = 0; e < 4; e++) acc[mt][nt][e] = 0.0f;

    float4 pa[4], pb[2][2];
#pragma unroll
    for (int it = 0; it < 4; it++)
        pa[it] = *(const float4*)(Ag + (size_t)it * 32 * K);
#pragma unroll
    for (int it = 0; it < 2; it++) {
        pb[it][0] = *(const float4*)(Bg + (size_t)(16 * it) * N);
        pb[it][1] = *(const float4*)(Bg + (size_t)(16 * it + 1) * N);
    }

#pragma unroll
    for (int it = 0; it < 4; it++) {
        uint32_t* ap = As + (arow + it * 32) * 20;
        ap[ap0] = pack_h2(pa[it].x, pa[it].y);
        ap[ap1] = pack_h2(pa[it].z, pa[it].w);
    }
#pragma unroll
    for (int it = 0; it < 2; it++) {
        uint4 w;
        w.x = pack_h2(pb[it][0].x * WSCALE, pb[it][1].x * WSCALE);
        w.y = pack_h2(pb[it][0].y * WSCALE, pb[it][1].y * WSCALE);
        w.z = pack_h2(pb[it][0].z * WSCALE, pb[it][1].z * WSCALE);
        w.w = pack_h2(pb[it][0].w * WSCALE, pb[it][1].w * WSCALE);
        *(uint4*)&Bs[(bj + it * 8) * 136 + bcol4] = w;
    }
    __syncthreads();

    const int nCh = K / GBK;
    for (int c = 0; c < nCh; c++) {
        const int b = c & 1;
        const uint32_t* as = As + b * AS_U32;
        const uint32_t* bs = Bs + b * BS_U32;

        if (c + 1 < nCh) {
            const int k0 = (c + 1) * GBK;
#pragma unroll
            for (int it = 0; it < 4; it++)
                pa[it] = *(const float4*)(Ag + k0 + (size_t)it * 32 * K);
#pragma unroll
            for (int it = 0; it < 2; it++) {
                pb[it][0] = *(const float4*)(Bg + (size_t)(k0 + 16 * it) * N);
                pb[it][1] = *(const float4*)(Bg + (size_t)(k0 + 16 * it + 1) * N);
            }
        }

#pragma unroll
        for (int kk = 0; kk < 2; kk++) {
            const int kw2 = kk * 8 + 2 * q;   // permuted: (w, w+4) adjacent
            uint32_t af[4][4], bf[4][2];
#pragma unroll
            for (int mt = 0; mt < 4; mt++) {
                const int r0 = warp_m * 64 + mt * 16 + g;
                uint2 x0 = *(const uint2*)&as[r0 * 20 + kw2];
                uint2 x1 = *(const uint2*)&as[(r0 + 8) * 20 + kw2];
                af[mt][0] = x0.x; af[mt][1] = x1.x;
                af[mt][2] = x0.y; af[mt][3] = x1.y;
            }
            const int kw = kk * 8;
#pragma unroll
            for (int nt = 0; nt < 4; nt++) {
                const int n = warp_n * 32 + nt * 8 + g;
                bf[nt][0] = bs[(kw + q) * 136 + n];
                bf[nt][1] = bs[(kw + q + 4) * 136 + n];
            }
#pragma unroll
            for (int mt = 0; mt < 4; mt++)
#pragma unroll
                for (int nt = 0; nt < 4; nt++)
                    mma_f16(acc[mt][nt], af[mt], bf[nt]);
        }

        if (c + 1 < nCh) {
            uint32_t* aw = As + (1 - b) * AS_U32;
            uint32_t* bw = Bs + (1 - b) * BS_U32;
#pragma unroll
            for (int it = 0; it < 4; it++) {
                uint32_t* ap = aw + (arow + it * 32) * 20;
                ap[ap0] = pack_h2(pa[it].x, pa[it].y);
                ap[ap1] = pack_h2(pa[it].z, pa[it].w);
            }
#pragma unroll
            for (int it = 0; it < 2; it++) {
                uint4 w;
                w.x = pack_h2(pb[it][0].x * WSCALE, pb[it][1].x * WSCALE);
                w.y = pack_h2(pb[it][0].y * WSCALE, pb[it][1].y * WSCALE);
                w.z = pack_h2(pb[it][0].z * WSCALE, pb[it][1].z * WSCALE);
                w.w = pack_h2(pb[it][0].w * WSCALE, pb[it][1].w * WSCALE);
                *(uint4*)&bw[(bj + it * 8) * 136 + bcol4] = w;
            }
        }
        __syncthreads();
    }

    // epilogue: descale weights (2^-6) + optional RoPE; thread owns pairs
    // (col, col+1) at rows (row, row+8)
#pragma unroll
    for (int mt = 0; mt < 4; mt++) {
        const int row = m0 + warp_m * 64 + mt * 16 + g;
        float p0 = 0.0f, p1 = 0.0f;
        if (ROPE_MODE) {
            p0 = (float)pos[row];
            p1 = (float)pos[row + 8];
        }
#pragma unroll
        for (int nt = 0; nt < 4; nt++) {
            const int col = n0 + warp_n * 32 + nt * 8 + q * 2;
            float v00 = acc[mt][nt][0] * WDESC, v01 = acc[mt][nt][1] * WDESC;
            float v10 = acc[mt][nt][2] * WDESC, v11 = acc[mt][nt][3] * WDESC;
            if (ROPE_MODE) {
                const int i = (col & 63) >> 1;   // RoPE pair index within head
                const float f = c_invfreq[i];
                float s0, c0, s1, c1;
                sincosf(p0 * f, &s0, &c0);
                sincosf(p1 * f, &s1, &c1);
                float o00 = fmaf(v00, c0, -v01 * s0);
                float o01 = fmaf(v00, s0,  v01 * c0);
                float o10 = fmaf(v10, c1, -v11 * s1);
                float o11 = fmaf(v10, s1,  v11 * c1);
                v00 = o00; v01 = o01; v10 = o10; v11 = o11;
            }
            *(float2*)(C + (size_t)row * N + col)       = make_float2(v00, v01);
            *(float2*)(C + (size_t)(row + 8) * N + col) = make_float2(v10, v11);
        }
    }
}

// Plain GEMM (O projection)
__global__ __launch_bounds__(256, 2)
void mma_gemm(const float* __restrict__ A, const float* __restrict__ B,
              float* __restrict__ C, int N, int K)
{
    extern __shared__ uint32_t smu[];
    gemm_core<0>(A, B, C, N, K, blockIdx.y * GBM, blockIdx.x * GBN, nullptr, smu);
}

// Fused QKV projection + RoPE.
// grid.x in [0,24): 0-15 -> Q (Wq, rope), 16-19 -> K (Wk, rope), 20-23 -> V (Wv).
__global__ __launch_bounds__(256, 2)
void mma_gemm_qkv(const float* __restrict__ X,
                  const float* __restrict__ Wq, const float* __restrict__ Wk,
                  const float* __restrict__ Wv,
                  float* __restrict__ Cq, float* __restrict__ Ck, float* __restrict__ Cv,
                  const int* __restrict__ pos)
{
    extern __shared__ uint32_t smu[];
    const int bx = blockIdx.x;
    const int m0 = blockIdx.y * GBM;
    if (bx < 16) {
        gemm_core<1>(X, Wq, Cq, DM, DM, m0, bx * GBN, pos, smu);
    } else if (bx < 20) {
        gemm_core<1>(X, Wk, Ck, KVD, DM, m0, (bx - 16) * GBN, pos, smu);
    } else {
        gemm_core<0>(X, Wv, Cv, KVD, DM, m0, (bx - 20) * GBN, nullptr, smu);
    }
}

// ==================================================================
// fp16 tensor-core flash attention, causal + mask, GQA.
// (EXACT round-13 configuration — best measured)
// ==================================================================
#define FA_K_PAD 36
#define FA_V_PAD 72
#define FA3_SMEM_U32 (64 * FA_K_PAD + 32 * FA_V_PAD + 64)
#define FA3_SMEM_BYTES (FA3_SMEM_U32 * 4)   // 18688

// 0.125 * log2(e)
#define QSCALE 0.180336880111120429f

__global__ __launch_bounds__(256, 2)
void fa_mma_kernel(const float* __restrict__ Q, const float* __restrict__ K,
                   const float* __restrict__ V, const int* __restrict__ mask,
                   float* __restrict__ Oout)
{
    extern __shared__ uint32_t su[];
    uint32_t* Ksp = su;                       // [64][36] words
    uint32_t* Vsp = Ksp + 64 * FA_K_PAD;      // [32][72] words (key-pairs)
    float*    kb  = (float*)(Vsp + 32 * FA_V_PAD);

    const int tid = threadIdx.x;
    const int wid = tid >> 5, lane = tid & 31;
    const int g = lane >> 2, q = lane & 3;
    // LPT: longest CTAs (highest qt) launch first
    const int qt = (gridDim.x - 1) - blockIdx.x;
    const int h = blockIdx.y, b = blockIdx.z;
    const int q0 = qt * 128;
    const int kvh = h >> 2;
    const int row0 = q0 + wid * 16 + g;

    // Q fragments (fp16, prescaled by 0.125*log2e)
    uint32_t qa[4][4];
    {
        const float* Qr0 = Q + ((size_t)(b * SEQ) + row0) * DM + h * HD;
        const float* Qr1 = Qr0 + (size_t)8 * DM;
#pragma unroll
        for (int k4 = 0; k4 < 4; k4++) {
            const int k0 = k4 * 16 + 2 * q;
            float2 x0 = *(const float2*)(Qr0 + k0);
            float2 x1 = *(const float2*)(Qr1 + k0);
            float2 x2 = *(const float2*)(Qr0 + k0 + 8);
            float2 x3 = *(const float2*)(Qr1 + k0 + 8);
            qa[k4][0] = pack_h2(x0.x * QSCALE, x0.y * QSCALE);
            qa[k4][1] = pack_h2(x1.x * QSCALE, x1.y * QSCALE);
            qa[k4][2] = pack_h2(x2.x * QSCALE, x2.y * QSCALE);
            qa[k4][3] = pack_h2(x3.x * QSCALE, x3.y * QSCALE);
        }
    }

    float m0r = -1e30f, m1r = -1e30f;
    float l0r = 0.0f,  l1r = 0.0f;
    float oc[8][4];
#pragma unroll
    for (int nt = 0; nt < 8; nt++)
#pragma unroll
        for (int e = 0; e < 4; e++) oc[nt][e] = 0.0f;

    // V loader indices (packed key-pairs)
    const int vj = tid >> 3;           // 0..31
    const int vd8 = (tid & 7) * 8;     // 0..56

    const int ktmax = 2 * qt + 1;
    for (int kt = 0; kt <= ktmax; kt++) {
        const int k0 = kt * 64;
        __syncthreads();

        // K tile: 64x64 fp32 -> [64][36] f16x2 words
#pragma unroll
        for (int it = 0; it < 4; it++) {
            int idx = tid + it * 256;
            int r = idx >> 4, c4 = (idx & 15) * 4;
            float4 kk = *(const float4*)(K + ((size_t)(b * SEQ) + k0 + r) * KVD + kvh * HD + c4);
            uint2 w;
            w.x = pack_h2(kk.x, kk.y);
            w.y = pack_h2(kk.z, kk.w);
            *(uint2*)&Ksp[r * 36 + (c4 >> 1)] = w;
        }
        // V tile: pack key-pairs (V[2j][d], V[2j+1][d]) -> Vsp[j][d]
        {
            const float* v0 = V + ((size_t)(b * SEQ) + k0 + 2 * vj) * KVD + kvh * HD + vd8;
            const float* v1 = v0 + KVD;
            float4 a0 = *(const float4*)v0, a1 = *(const float4*)(v0 + 4);
            float4 b0 = *(const float4*)v1, b1 = *(const float4*)(v1 + 4);
            uint4 w0, w1;
            w0.x = pack_h2(a0.x, b0.x); w0.y = pack_h2(a0.y, b0.y);
            w0.z = pack_h2(a0.z, b0.z); w0.w = pack_h2(a0.w, b0.w);
            w1.x = pack_h2(a1.x, b1.x); w1.y = pack_h2(a1.y, b1.y);
            w1.z = pack_h2(a1.z, b1.z); w1.w = pack_h2(a1.w, b1.w);
            *(uint4*)&Vsp[vj * FA_V_PAD + vd8] = w0;
            *(uint4*)&Vsp[vj * FA_V_PAD + vd8 + 4] = w1;
        }
        if (tid < 64)
            kb[tid] = (mask[b * SEQ + k0 + tid] > 0) ? 0.0f : -1e30f;
        __syncthreads();

        // S = (Q*qscale) @ K^T   (4 ksteps of K=16)
        float sc[8][4];
#pragma unroll
        for (int nt = 0; nt < 8; nt++)
#pragma unroll
            for (int e = 0; e < 4; e++) sc[nt][e] = 0.0f;

#pragma unroll
        for (int k4 = 0; k4 < 4; k4++) {
            const int kw = k4 * 8;
#pragma unroll
            for (int nt = 0; nt < 8; nt++) {
                uint32_t bq[2];
                bq[0] = Ksp[(nt * 8 + g) * 36 + kw + q];
                bq[1] = Ksp[(nt * 8 + g) * 36 + kw + q + 4];
                mma_f16(sc[nt], qa[k4], bq);
            }
        }

        // causal + mask bias
#pragma unroll
        for (int nt = 0; nt < 8; nt++) {
            const int c0 = k0 + nt * 8 + 2 * q;
            const float kb0 = kb[nt * 8 + 2 * q];
            const float kb1 = kb[nt * 8 + 2 * q + 1];
            sc[nt][0] = (c0     <= row0    ) ? sc[nt][0] + kb0 : -1e30f;
            sc[nt][1] = (c0 + 1 <= row0    ) ? sc[nt][1] + kb1 : -1e30f;
            sc[nt][2] = (c0     <= row0 + 8) ? sc[nt][2] + kb0 : -1e30f;
            sc[nt][3] = (c0 + 1 <= row0 + 8) ? sc[nt][3] + kb1 : -1e30f;
        }

        float mx0 = -1e30f, mx1 = -1e30f;
#pragma unroll
        for (int nt = 0; nt < 8; nt++) {
            mx0 = fmaxf(mx0, fmaxf(sc[nt][0], sc[nt][1]));
            mx1 = fmaxf(mx1, fmaxf(sc[nt][2], sc[nt][3]));
        }
        mx0 = fmaxf(mx0, __shfl_xor_sync(0xffffffffu, mx0, 1));
        mx0 = fmaxf(mx0, __shfl_xor_sync(0xffffffffu, mx0, 2));
        mx1 = fmaxf(mx1, __shfl_xor_sync(0xffffffffu, mx1, 1));
        mx1 = fmaxf(mx1, __shfl_xor_sync(0xffffffffu, mx1, 2));

        const float mn0 = fmaxf(m0r, mx0);
        const float mn1 = fmaxf(m1r, mx1);
        const float al0 = ex2f(m0r - mn0);   // base-2 domain
        const float al1 = ex2f(m1r - mn1);
        m0r = mn0; m1r = mn1;

        // P = exp2(S - m), packed straight into fp16 A-fragments (registers)
        uint32_t pf[4][4];
        float s0 = 0.0f, s1 = 0.0f;
#pragma unroll
        for (int nt = 0; nt < 8; nt++) {
            float p0 = ex2f(sc[nt][0] - mn0);
            float p1 = ex2f(sc[nt][1] - mn0);
            float p2 = ex2f(sc[nt][2] - mn1);
            float p3 = ex2f(sc[nt][3] - mn1);
            s0 += p0 + p1; s1 += p2 + p3;
            const int k4 = nt >> 1;
            if (nt & 1) {
                pf[k4][2] = pack_h2(p0, p1);
                pf[k4][3] = pack_h2(p2, p3);
            } else {
                pf[k4][0] = pack_h2(p0, p1);
                pf[k4][1] = pack_h2(p2, p3);
            }
        }
        s0 += __shfl_xor_sync(0xffffffffu, s0, 1);
        s0 += __shfl_xor_sync(0xffffffffu, s0, 2);
        s1 += __shfl_xor_sync(0xffffffffu, s1, 1);
        s1 += __shfl_xor_sync(0xffffffffu, s1, 2);
        l0r = al0 * l0r + s0;
        l1r = al1 * l1r + s1;

#pragma unroll
        for (int nt = 0; nt < 8; nt++) {
            oc[nt][0] *= al0; oc[nt][1] *= al0;
            oc[nt][2] *= al1; oc[nt][3] *= al1;
        }

        // O += P @ V  (4 ksteps of K=16; A in registers)
#pragma unroll
        for (int k4 = 0; k4 < 4; k4++) {
#pragma unroll
            for (int nt = 0; nt < 8; nt++) {
                uint32_t bv[2];
                bv[0] = Vsp[(k4 * 8 + q) * FA_V_PAD + nt * 8 + g];
                bv[1] = Vsp[(k4 * 8 + q + 4) * FA_V_PAD + nt * 8 + g];
                mma_f16(oc[nt], pf[k4], bv);
            }
        }
    }

    const float inv0 = 1.0f / l0r;
    const float inv1 = 1.0f / l1r;
    float* O0 = Oout + ((size_t)(b * SEQ) + row0) * DM + h * HD;
    float* O1 = O0 + (size_t)8 * DM;
#pragma unroll
    for (int nt = 0; nt < 8; nt++) {
        const int col = nt * 8 + 2 * q;
        *(float2*)(O0 + col) = make_float2(oc[nt][0] * inv0, oc[nt][1] * inv0);
        *(float2*)(O1 + col) = make_float2(oc[nt][2] * inv1, oc[nt][3] * inv1);
    }
}

// ------------------------------------------------------------------
// Launch
// ------------------------------------------------------------------
extern "C" void kernel_launch(void* const* d_in, const int* in_sizes, int n_in,
                              void* d_out, int out_size)
{
    (void)in_sizes; (void)n_in; (void)out_size;
    const float* X    = (const float*)d_in[0];
    const int*   mask = (const int*)  d_in[1];
    const int*   pos  = (const int*)  d_in[2];
    const float* Wq   = (const float*)d_in[3];
    const float* Wk   = (const float*)d_in[4];
    const float* Wv   = (const float*)d_in[5];
    const float* Wo   = (const float*)d_in[6];
    float* out = (float*)d_out;

    float *q, *k, *v, *attn;
    cudaGetSymbolAddress((void**)&q,    g_q);
    cudaGetSymbolAddress((void**)&k,    g_k);
    cudaGetSymbolAddress((void**)&v,    g_v);
    cudaGetSymbolAddress((void**)&attn, g_attn);

    cudaFuncSetAttribute(mma_gemm, cudaFuncAttributeMaxDynamicSharedMemorySize, GEMM_SMEM_BYTES);
    cudaFuncSetAttribute(mma_gemm_qkv, cudaFuncAttributeMaxDynamicSharedMemorySize, GEMM_SMEM_BYTES);
    cudaFuncSetAttribute(fa_mma_kernel, cudaFuncAttributeMaxDynamicSharedMemorySize, FA3_SMEM_BYTES);

    // Fused QKV projections + RoPE (24 column tiles: 16 Q, 4 K, 4 V)
    mma_gemm_qkv<<<dim3(24, TOK / GBM), 256, GEMM_SMEM_BYTES>>>(X, Wq, Wk, Wv, q, k, v, pos);

    // fp16 tensor-core flash attention (P register-resident, LPT order)
    fa_mma_kernel<<<dim3(SEQ / 128, NH, BATCH), 256, FA3_SMEM_BYTES>>>(q, k, v, mask, attn);

    // Output projection
    mma_gemm<<<dim3(DM / GBN, TOK / GBM), 256, GEMM_SMEM_BYTES>>>(attn, Wo, out, DM, DM);
}

// round 15
// speedup vs baseline: 1.1760x; 1.1760x over previous
#include <cuda_runtime.h>
#include <cuda_fp16.h>
#include <cstdint>
#include <cstddef>

// Problem constants
#define SEQ   2048
#define BATCH 2
#define TOK   (SEQ * BATCH)   // 4096
#define DM    2048
#define NH    32
#define NKV   8
#define HD    64
#define KVD   (NKV * HD)      // 512

// ------------------------------------------------------------------
// Scratch (device globals; no cudaMalloc allowed)
// ------------------------------------------------------------------
__device__ float g_q[(size_t)TOK * DM];
__device__ float g_k[(size_t)TOK * KVD];
__device__ float g_v[(size_t)TOK * KVD];
__device__ float g_attn[(size_t)TOK * DM];

// Exact fp32 rounding of 10000^(-i/32), i = 0..31
__device__ __constant__ float c_invfreq[32] = {
    1.0f, 0.7498942093324559f, 0.5623413251903491f, 0.4216965034285822f,
    0.31622776601683794f, 0.23713737056616552f, 0.17782794100389228f, 0.1333521432163324f,
    0.1f, 0.07498942093324559f, 0.05623413251903491f, 0.04216965034285822f,
    0.031622776601683794f, 0.023713737056616552f, 0.017782794100389228f, 0.01333521432163324f,
    0.01f, 0.007498942093324559f, 0.005623413251903491f, 0.004216965034285822f,
    0.0031622776601683794f, 0.0023713737056616552f, 0.0017782794100389228f, 0.001333521432163324f,
    0.001f, 0.0007498942093324559f, 0.0005623413251903491f, 0.0004216965034285822f,
    0.00031622776601683794f, 0.00023713737056616552f, 0.00017782794100389228f, 0.0001333521432163324f
};

// ------------------------------------------------------------------
// fp16 helpers (baseline PTX, works on compute_103 virtual arch)
// ------------------------------------------------------------------
__device__ __forceinline__ uint32_t pack_h2(float lo, float hi) {
    __half2 h = __floats2half2_rn(lo, hi);
    return *reinterpret_cast<uint32_t*>(&h);
}
__device__ __forceinline__ float ex2f(float x) {
    float r;
    asm("ex2.approx.f32 %0, %1;" : "=f"(r) : "f"(x));
    return r;
}
__device__ __forceinline__ void mma_f16(float c[4], const uint32_t a[4], const uint32_t b[2]) {
    asm volatile("mma.sync.aligned.m16n8k16.row.col.f32.f16.f16.f32 "
                 "{%0,%1,%2,%3}, {%4,%5,%6,%7}, {%8,%9}, {%0,%1,%2,%3};"
                 : "+f"(c[0]), "+f"(c[1]), "+f"(c[2]), "+f"(c[3])
                 : "r"(a[0]), "r"(a[1]), "r"(a[2]), "r"(a[3]), "r"(b[0]), "r"(b[1]));
}
__device__ __forceinline__ void mma_f16_b2(float c[4], const uint32_t a[4],
                                           uint32_t b0, uint32_t b1) {
    asm volatile("mma.sync.aligned.m16n8k16.row.col.f32.f16.f16.f32 "
                 "{%0,%1,%2,%3}, {%4,%5,%6,%7}, {%8,%9}, {%0,%1,%2,%3};"
                 : "+f"(c[0]), "+f"(c[1]), "+f"(c[2]), "+f"(c[3])
                 : "r"(a[0]), "r"(a[1]), "r"(a[2]), "r"(a[3]), "r"(b0), "r"(b1));
}
__device__ __forceinline__ uint32_t smem_u32(const void* p) {
    uint32_t r;
    asm("{ .reg .u64 t; cvta.to.shared.u64 t, %1; cvt.u32.u64 %0, t; }" : "=r"(r) : "l"(p));
    return r;
}
#define LDMATRIX_X4(r0, r1, r2, r3, addr) \
    asm volatile("ldmatrix.sync.aligned.m8n8.x4.shared.b16 {%0,%1,%2,%3}, [%4];" \
                 : "=r"(r0), "=r"(r1), "=r"(r2), "=r"(r3) : "r"(addr))

// Weight scale 2^6 (exact) to avoid fp16 subnormals; descale in epilogue.
#define WSCALE 64.0f
#define WDESC  0.015625f

// ==================================================================
// fp16 mma.sync GEMM core — R13 configuration (best measured) with
// A-fragment loads via ldmatrix.x4 (issue count 32 -> 8 per warp/chunk;
// pad 20 words is conflict-free for ldmatrix: 20r mod 32 spans disjoint).
// CTA tile 256x128, K-chunk 32, 512 threads = 16 warps (4m x 4n),
// warp tile 64x32, LDG register prefetch + cvt-on-store, double buffer.
// ==================================================================
#define GBM 256
#define GBN 128
#define GBK 32
#define AS_U32 (256 * 20)   // 5120 words
#define BS_U32 (16 * 136)   // 2176 words
#define GEMM_SMEM_BYTES ((AS_U32 + BS_U32) * 2 * 4)  // 58368

template <int ROPE_MODE>
__device__ __forceinline__ void gemm_core(
    const float* __restrict__ A, const float* __restrict__ B,
    float* __restrict__ C, int N, int K, int m0, int n0,
    const int* __restrict__ pos, uint32_t* smu)
{
    uint32_t* As = smu;                 // 2 buffers
    uint32_t* Bs = smu + 2 * AS_U32;
    const uint32_t sA = smem_u32(As);

    const int tid = threadIdx.x;
    const int wid = tid >> 5, lane = tid & 31;
    const int g = lane >> 2, q = lane & 3;
    const int warp_m = wid >> 2;           // 0..3 (64 rows)
    const int warp_n = wid & 3;            // 0..3 (32 cols)

    // ldmatrix per-lane addressing for A fragments:
    // lanes 0-15 -> rows (lane&15), col kw; lanes 16-31 -> rows, col kw+4
    const int lrow = lane & 15;
    const int lcol = (lane >> 4) * 4;
    uint32_t a_lm[4];
#pragma unroll
    for (int mt = 0; mt < 4; mt++)
        a_lm[mt] = sA + (uint32_t)(((warp_m * 64 + mt * 16 + lrow) * 20 + lcol) * 4);

    // loaders: A 256x32 (4 float4/thread), B 32x128 as 16 k-pairs (2 float4/thread)
    const int arow = tid >> 3;             // 0..63
    const int acol4 = (tid & 7) * 4;
    const int aw0 = (tid & 7) * 2;         // word offset in A row
    const int bj = tid >> 5;               // 0..15 (k-pair index)
    const int bcol4 = (tid & 31) * 4;
    const float* Ag = A + (size_t)(m0 + arow) * K + acol4;
    const float* Bg = B + (size_t)(2 * bj) * N + n0 + bcol4;

    float acc[4][4][4];
#pragma unroll
    for (int mt = 0; mt < 4; mt++)
#pragma unroll
        for (int nt = 0; nt < 4; nt++)
#pragma unroll
            for (int e = 0; e < 4; e++) acc[mt][nt][e] = 0.0f;

    float4 pa[4], pb0, pb1;
#pragma unroll
    for (int it = 0; it < 4; it++)
        pa[it] = *(const float4*)(Ag + (size_t)it * 64 * K);
    pb0 = *(const float4*)(Bg);
    pb1 = *(const float4*)(Bg + N);

#pragma unroll
    for (int it = 0; it < 4; it++) {
        uint2 w;
        w.x = pack_h2(pa[it].x, pa[it].y);
        w.y = pack_h2(pa[it].z, pa[it].w);
        *(uint2*)&As[(arow + it * 64) * 20 + aw0] = w;
    }
    {
        uint4 w;
        w.x = pack_h2(pb0.x * WSCALE, pb1.x * WSCALE);
        w.y = pack_h2(pb0.y * WSCALE, pb1.y * WSCALE);
        w.z = pack_h2(pb0.z * WSCALE, pb1.z * WSCALE);
        w.w = pack_h2(pb0.w * WSCALE, pb1.w * WSCALE);
        *(uint4*)&Bs[bj * 136 + bcol4] = w;
    }
    __syncthreads();

    const int nCh = K / GBK;
    for (int c = 0; c < nCh; c++) {
        const int b = c & 1;
        const uint32_t aOff = (uint32_t)(b * AS_U32 * 4);
        const uint32_t* bs = Bs + b * BS_U32;

        if (c + 1 < nCh) {
            const int k0 = (c + 1) * GBK;
#pragma unroll
            for (int it = 0; it < 4; it++)
                pa[it] = *(const float4*)(Ag + k0 + (size_t)it * 64 * K);
            pb0 = *(const float4*)(Bg + (size_t)k0 * N);
            pb1 = *(const float4*)(Bg + (size_t)(k0 + 1) * N);
        }

#pragma unroll
        for (int kk = 0; kk < 2; kk++) {
            const int kw = kk * 8;
            uint32_t af[4][4], bf[4][2];
#pragma unroll
            for (int mt = 0; mt < 4; mt++)
                LDMATRIX_X4(af[mt][0], af[mt][1], af[mt][2], af[mt][3],
                            a_lm[mt] + aOff + (uint32_t)(kw * 4));
#pragma unroll
            for (int nt = 0; nt < 4; nt++) {
                const int n = warp_n * 32 + nt * 8 + g;
                bf[nt][0] = bs[(kw + q) * 136 + n];
                bf[nt][1] = bs[(kw + q + 4) * 136 + n];
            }
#pragma unroll
            for (int mt = 0; mt < 4; mt++)
#pragma unroll
                for (int nt = 0; nt < 4; nt++)
                    mma_f16(acc[mt][nt], af[mt], bf[nt]);
        }

        if (c + 1 < nCh) {
            uint32_t* aw = As + (1 - b) * AS_U32;
            uint32_t* bw = Bs + (1 - b) * BS_U32;
#pragma unroll
            for (int it = 0; it < 4; it++) {
                uint2 w;
                w.x = pack_h2(pa[it].x, pa[it].y);
                w.y = pack_h2(pa[it].z, pa[it].w);
                *(uint2*)&aw[(arow + it * 64) * 20 + aw0] = w;
            }
            uint4 w;
            w.x = pack_h2(pb0.x * WSCALE, pb1.x * WSCALE);
            w.y = pack_h2(pb0.y * WSCALE, pb1.y * WSCALE);
            w.z = pack_h2(pb0.z * WSCALE, pb1.z * WSCALE);
            w.w = pack_h2(pb0.w * WSCALE, pb1.w * WSCALE);
            *(uint4*)&bw[bj * 136 + bcol4] = w;
        }
        __syncthreads();
    }

    // epilogue: descale weights (2^-6) + optional RoPE; thread owns pairs
    // (col, col+1) at rows (row, row+8)
#pragma unroll
    for (int mt = 0; mt < 4; mt++) {
        const int row = m0 + warp_m * 64 + mt * 16 + g;
        float p0 = 0.0f, p1 = 0.0f;
        if (ROPE_MODE) {
            p0 = (float)pos[row];
            p1 = (float)pos[row + 8];
        }
#pragma unroll
        for (int nt = 0; nt < 4; nt++) {
            const int col = n0 + warp_n * 32 + nt * 8 + q * 2;
            float v00 = acc[mt][nt][0] * WDESC, v01 = acc[mt][nt][1] * WDESC;
            float v10 = acc[mt][nt][2] * WDESC, v11 = acc[mt][nt][3] * WDESC;
            if (ROPE_MODE) {
                const int i = (col & 63) >> 1;   // RoPE pair index within head
                const float f = c_invfreq[i];
                float s0, c0, s1, c1;
                sincosf(p0 * f, &s0, &c0);
                sincosf(p1 * f, &s1, &c1);
                float o00 = fmaf(v00, c0, -v01 * s0);
                float o01 = fmaf(v00, s0,  v01 * c0);
                float o10 = fmaf(v10, c1, -v11 * s1);
                float o11 = fmaf(v10, s1,  v11 * c1);
                v00 = o00; v01 = o01; v10 = o10; v11 = o11;
            }
            *(float2*)(C + (size_t)row * N + col)       = make_float2(v00, v01);
            *(float2*)(C + (size_t)(row + 8) * N + col) = make_float2(v10, v11);
        }
    }
}

// Plain GEMM (O projection)
__global__ __launch_bounds__(512, 1)
void mma_gemm(const float* __restrict__ A, const float* __restrict__ B,
              float* __restrict__ C, int N, int K)
{
    extern __shared__ uint32_t smu[];
    gemm_core<0>(A, B, C, N, K, blockIdx.y * GBM, blockIdx.x * GBN, nullptr, smu);
}

// Fused QKV projection + RoPE.
// grid.x in [0,24): 0-15 -> Q (Wq, rope), 16-19 -> K (Wk, rope), 20-23 -> V (Wv).
__global__ __launch_bounds__(512, 1)
void mma_gemm_qkv(const float* __restrict__ X,
                  const float* __restrict__ Wq, const float* __restrict__ Wk,
                  const float* __restrict__ Wv,
                  float* __restrict__ Cq, float* __restrict__ Ck, float* __restrict__ Cv,
                  const int* __restrict__ pos)
{
    extern __shared__ uint32_t smu[];
    const int bx = blockIdx.x;
    const int m0 = blockIdx.y * GBM;
    if (bx < 16) {
        gemm_core<1>(X, Wq, Cq, DM, DM, m0, bx * GBN, pos, smu);
    } else if (bx < 20) {
        gemm_core<1>(X, Wk, Ck, KVD, DM, m0, (bx - 16) * GBN, pos, smu);
    } else {
        gemm_core<0>(X, Wv, Cv, KVD, DM, m0, (bx - 20) * GBN, nullptr, smu);
    }
}

// ==================================================================
// fp16 tensor-core flash attention (R13 config) with K-fragment loads
// via ldmatrix.x4 (bq issues 64 -> 16 per warp/tile; pad 36 words is
// conflict-free: 36n mod 32 = 4n, disjoint 4-word spans).
// ==================================================================
#define FA_K_PAD 36
#define FA_V_PAD 72
#define FA3_SMEM_U32 (64 * FA_K_PAD + 32 * FA_V_PAD + 64)
#define FA3_SMEM_BYTES (FA3_SMEM_U32 * 4)   // 18688

// 0.125 * log2(e)
#define QSCALE 0.180336880111120429f

__global__ __launch_bounds__(256, 2)
void fa_mma_kernel(const float* __restrict__ Q, const float* __restrict__ K,
                   const float* __restrict__ V, const int* __restrict__ mask,
                   float* __restrict__ Oout)
{
    extern __shared__ uint32_t su[];
    uint32_t* Ksp = su;                       // [64][36] words
    uint32_t* Vsp = Ksp + 64 * FA_K_PAD;      // [32][72] words (key-pairs)
    float*    kb  = (float*)(Vsp + 32 * FA_V_PAD);
    const uint32_t sK = smem_u32(Ksp);

    const int tid = threadIdx.x;
    const int wid = tid >> 5, lane = tid & 31;
    const int g = lane >> 2, q = lane & 3;
    // LPT: longest CTAs (highest qt) launch first
    const int qt = (gridDim.x - 1) - blockIdx.x;
    const int h = blockIdx.y, b = blockIdx.z;
    const int q0 = qt * 128;
    const int kvh = h >> 2;
    const int row0 = q0 + wid * 16 + g;

    // ldmatrix lane addressing for K fragments:
    // tiles (ntA,kw), (ntA,kw+4), (ntB,kw), (ntB,kw+4); ntA=2p, ntB=2p+1
    const int krowsel = (lane & 7) + ((lane >> 4) * 8);
    const int kcoladd = ((lane >> 3) & 1) * 4;
    const uint32_t k_lm = sK + (uint32_t)((krowsel * FA_K_PAD + kcoladd) * 4);

    // Q fragments (fp16, prescaled by 0.125*log2e)
    uint32_t qa[4][4];
    {
        const float* Qr0 = Q + ((size_t)(b * SEQ) + row0) * DM + h * HD;
        const float* Qr1 = Qr0 + (size_t)8 * DM;
#pragma unroll
        for (int k4 = 0; k4 < 4; k4++) {
            const int k0 = k4 * 16 + 2 * q;
            float2 x0 = *(const float2*)(Qr0 + k0);
            float2 x1 = *(const float2*)(Qr1 + k0);
            float2 x2 = *(const float2*)(Qr0 + k0 + 8);
            float2 x3 = *(const float2*)(Qr1 + k0 + 8);
            qa[k4][0] = pack_h2(x0.x * QSCALE, x0.y * QSCALE);
            qa[k4][1] = pack_h2(x1.x * QSCALE, x1.y * QSCALE);
            qa[k4][2] = pack_h2(x2.x * QSCALE, x2.y * QSCALE);
            qa[k4][3] = pack_h2(x3.x * QSCALE, x3.y * QSCALE);
        }
    }

    float m0r = -1e30f, m1r = -1e30f;
    float l0r = 0.0f,  l1r = 0.0f;
    float oc[8][4];
#pragma unroll
    for (int nt = 0; nt < 8; nt++)
#pragma unroll
        for (int e = 0; e < 4; e++) oc[nt][e] = 0.0f;

    // V loader indices (packed key-pairs)
    const int vj = tid >> 3;           // 0..31
    const int vd8 = (tid & 7) * 8;     // 0..56

    const int ktmax = 2 * qt + 1;
    for (int kt = 0; kt <= ktmax; kt++) {
        const int k0 = kt * 64;
        __syncthreads();

        // K tile: 64x64 fp32 -> [64][36] f16x2 words
#pragma unroll
        for (int it = 0; it < 4; it++) {
            int idx = tid + it * 256;
            int r = idx >> 4, c4 = (idx & 15) * 4;
            float4 kk = *(const float4*)(K + ((size_t)(b * SEQ) + k0 + r) * KVD + kvh * HD + c4);
            uint2 w;
            w.x = pack_h2(kk.x, kk.y);
            w.y = pack_h2(kk.z, kk.w);
            *(uint2*)&Ksp[r * 36 + (c4 >> 1)] = w;
        }
        // V tile: pack key-pairs (V[2j][d], V[2j+1][d]) -> Vsp[j][d]
        {
            const float* v0 = V + ((size_t)(b * SEQ) + k0 + 2 * vj) * KVD + kvh * HD + vd8;
            const float* v1 = v0 + KVD;
            float4 a0 = *(const float4*)v0, a1 = *(const float4*)(v0 + 4);
            float4 b0 = *(const float4*)v1, b1 = *(const float4*)(v1 + 4);
            uint4 w0, w1;
            w0.x = pack_h2(a0.x, b0.x); w0.y = pack_h2(a0.y, b0.y);
            w0.z = pack_h2(a0.z, b0.z); w0.w = pack_h2(a0.w, b0.w);
            w1.x = pack_h2(a1.x, b1.x); w1.y = pack_h2(a1.y, b1.y);
            w1.z = pack_h2(a1.z, b1.z); w1.w = pack_h2(a1.w, b1.w);
            *(uint4*)&Vsp[vj * FA_V_PAD + vd8] = w0;
            *(uint4*)&Vsp[vj * FA_V_PAD + vd8 + 4] = w1;
        }
        if (tid < 64)
            kb[tid] = (mask[b * SEQ + k0 + tid] > 0) ? 0.0f : -1e30f;
        __syncthreads();

        // S = (Q*qscale) @ K^T   (4 ksteps of K=16; K frags via ldmatrix)
        float sc[8][4];
#pragma unroll
        for (int nt = 0; nt < 8; nt++)
#pragma unroll
            for (int e = 0; e < 4; e++) sc[nt][e] = 0.0f;

#pragma unroll
        for (int k4 = 0; k4 < 4; k4++) {
#pragma unroll
            for (int p = 0; p < 4; p++) {
                uint32_t r0, r1, r2, r3;
                LDMATRIX_X4(r0, r1, r2, r3,
                            k_lm + (uint32_t)(((p * 16) * FA_K_PAD + k4 * 8) * 4));
                mma_f16_b2(sc[2 * p],     qa[k4], r0, r1);
                mma_f16_b2(sc[2 * p + 1], qa[k4], r2, r3);
            }
        }

        // causal + mask bias
#pragma unroll
        for (int nt = 0; nt < 8; nt++) {
            const int c0 = k0 + nt * 8 + 2 * q;
            const float kb0 = kb[nt * 8 + 2 * q];
            const float kb1 = kb[nt * 8 + 2 * q + 1];
            sc[nt][0] = (c0     <= row0    ) ? sc[nt][0] + kb0 : -1e30f;
            sc[nt][1] = (c0 + 1 <= row0    ) ? sc[nt][1] + kb1 : -1e30f;
            sc[nt][2] = (c0     <= row0 + 8) ? sc[nt][2] + kb0 : -1e30f;
            sc[nt][3] = (c0 + 1 <= row0 + 8) ? sc[nt][3] + kb1 : -1e30f;
        }

        float mx0 = -1e30f, mx1 = -1e30f;
#pragma unroll
        for (int nt = 0; nt < 8; nt++) {
            mx0 = fmaxf(mx0, fmaxf(sc[nt][0], sc[nt][1]));
            mx1 = fmaxf(mx1, fmaxf(sc[nt][2], sc[nt][3]));
        }
        mx0 = fmaxf(mx0, __shfl_xor_sync(0xffffffffu, mx0, 1));
        mx0 = fmaxf(mx0, __shfl_xor_sync(0xffffffffu, mx0, 2));
        mx1 = fmaxf(mx1, __shfl_xor_sync(0xffffffffu, mx1, 1));
        mx1 = fmaxf(mx1, __shfl_xor_sync(0xffffffffu, mx1, 2));

        const float mn0 = fmaxf(m0r, mx0);
        const float mn1 = fmaxf(m1r, mx1);
        const float al0 = ex2f(m0r - mn0);   // base-2 domain
        const float al1 = ex2f(m1r - mn1);
        m0r = mn0; m1r = mn1;

        // P = exp2(S - m), packed straight into fp16 A-fragments (registers)
        uint32_t pf[4][4];
        float s0 = 0.0f, s1 = 0.0f;
#pragma unroll
        for (int nt = 0; nt < 8; nt++) {
            float p0 = ex2f(sc[nt][0] - mn0);
            float p1 = ex2f(sc[nt][1] - mn0);
            float p2 = ex2f(sc[nt][2] - mn1);
            float p3 = ex2f(sc[nt][3] - mn1);
            s0 += p0 + p1; s1 += p2 + p3;
            const int k4 = nt >> 1;
            if (nt & 1) {
                pf[k4][2] = pack_h2(p0, p1);
                pf[k4][3] = pack_h2(p2, p3);
            } else {
                pf[k4][0] = pack_h2(p0, p1);
                pf[k4][1] = pack_h2(p2, p3);
            }
        }
        s0 += __shfl_xor_sync(0xffffffffu, s0, 1);
        s0 += __shfl_xor_sync(0xffffffffu, s0, 2);
        s1 += __shfl_xor_sync(0xffffffffu, s1, 1);
        s1 += __shfl_xor_sync(0xffffffffu, s1, 2);
        l0r = al0 * l0r + s0;
        l1r = al1 * l1r + s1;

#pragma unroll
        for (int nt = 0; nt < 8; nt++) {
            oc[nt][0] *= al0; oc[nt][1] *= al0;
            oc[nt][2] *= al1; oc[nt][3] *= al1;
        }

        // O += P @ V  (4 ksteps of K=16; A in registers)
#pragma unroll
        for (int k4 = 0; k4 < 4; k4++) {
#pragma unroll
            for (int nt = 0; nt < 8; nt++) {
                uint32_t bv[2];
                bv[0] = Vsp[(k4 * 8 + q) * FA_V_PAD + nt * 8 + g];
                bv[1] = Vsp[(k4 * 8 + q + 4) * FA_V_PAD + nt * 8 + g];
                mma_f16(oc[nt], pf[k4], bv);
            }
        }
    }

    const float inv0 = 1.0f / l0r;
    const float inv1 = 1.0f / l1r;
    float* O0 = Oout + ((size_t)(b * SEQ) + row0) * DM + h * HD;
    float* O1 = O0 + (size_t)8 * DM;
#pragma unroll
    for (int nt = 0; nt < 8; nt++) {
        const int col = nt * 8 + 2 * q;
        *(float2*)(O0 + col) = make_float2(oc[nt][0] * inv0, oc[nt][1] * inv0);
        *(float2*)(O1 + col) = make_float2(oc[nt][2] * inv1, oc[nt][3] * inv1);
    }
}

// ------------------------------------------------------------------
// Launch
// ------------------------------------------------------------------
extern "C" void kernel_launch(void* const* d_in, const int* in_sizes, int n_in,
                              void* d_out, int out_size)
{
    (void)in_sizes; (void)n_in; (void)out_size;
    const float* X    = (const float*)d_in[0];
    const int*   mask = (const int*)  d_in[1];
    const int*   pos  = (const int*)  d_in[2];
    const float* Wq   = (const float*)d_in[3];
    const float* Wk   = (const float*)d_in[4];
    const float* Wv   = (const float*)d_in[5];
    const float* Wo   = (const float*)d_in[6];
    float* out = (float*)d_out;

    float *q, *k, *v, *attn;
    cudaGetSymbolAddress((void**)&q,    g_q);
    cudaGetSymbolAddress((void**)&k,    g_k);
    cudaGetSymbolAddress((void**)&v,    g_v);
    cudaGetSymbolAddress((void**)&attn, g_attn);

    cudaFuncSetAttribute(mma_gemm, cudaFuncAttributeMaxDynamicSharedMemorySize, GEMM_SMEM_BYTES);
    cudaFuncSetAttribute(mma_gemm_qkv, cudaFuncAttributeMaxDynamicSharedMemorySize, GEMM_SMEM_BYTES);
    cudaFuncSetAttribute(fa_mma_kernel, cudaFuncAttributeMaxDynamicSharedMemorySize, FA3_SMEM_BYTES);

    // Fused QKV projections + RoPE (24 column tiles: 16 Q, 4 K, 4 V)
    mma_gemm_qkv<<<dim3(24, TOK / GBM), 512, GEMM_SMEM_BYTES>>>(X, Wq, Wk, Wv, q, k, v, pos);

    // fp16 tensor-core flash attention (ldmatrix K frags, P register-resident)
    fa_mma_kernel<<<dim3(SEQ / 128, NH, BATCH), 256, FA3_SMEM_BYTES>>>(q, k, v, mask, attn);

    // Output projection
    mma_gemm<<<dim3(DM / GBN, TOK / GBM), 512, GEMM_SMEM_BYTES>>>(attn, Wo, out, DM, DM);
}

// round 16
// speedup vs baseline: 1.2958x; 1.1019x over previous
#include <cuda_runtime.h>
#include <cuda_fp16.h>
#include <cstdint>
#include <cstddef>

// Problem constants
#define SEQ   2048
#define BATCH 2
#define TOK   (SEQ * BATCH)   // 4096
#define DM    2048
#define NH    32
#define NKV   8
#define HD    64
#define KVD   (NKV * HD)      // 512

// ------------------------------------------------------------------
// Scratch (device globals; no cudaMalloc allowed)
// ------------------------------------------------------------------
__device__ float g_q[(size_t)TOK * DM];
__device__ float g_k[(size_t)TOK * KVD];
__device__ float g_v[(size_t)TOK * KVD];
__device__ float g_attn[(size_t)TOK * DM];

// Exact fp32 rounding of 10000^(-i/32), i = 0..31
__device__ __constant__ float c_invfreq[32] = {
    1.0f, 0.7498942093324559f, 0.5623413251903491f, 0.4216965034285822f,
    0.31622776601683794f, 0.23713737056616552f, 0.17782794100389228f, 0.1333521432163324f,
    0.1f, 0.07498942093324559f, 0.05623413251903491f, 0.04216965034285822f,
    0.031622776601683794f, 0.023713737056616552f, 0.017782794100389228f, 0.01333521432163324f,
    0.01f, 0.007498942093324559f, 0.005623413251903491f, 0.004216965034285822f,
    0.0031622776601683794f, 0.0023713737056616552f, 0.0017782794100389228f, 0.001333521432163324f,
    0.001f, 0.0007498942093324559f, 0.0005623413251903491f, 0.0004216965034285822f,
    0.00031622776601683794f, 0.00023713737056616552f, 0.00017782794100389228f, 0.0001333521432163324f
};

// ------------------------------------------------------------------
// fp16 helpers (baseline PTX, works on compute_103 virtual arch)
// ------------------------------------------------------------------
__device__ __forceinline__ uint32_t pack_h2(float lo, float hi) {
    __half2 h = __floats2half2_rn(lo, hi);
    return *reinterpret_cast<uint32_t*>(&h);
}
__device__ __forceinline__ float ex2f(float x) {
    float r;
    asm("ex2.approx.f32 %0, %1;" : "=f"(r) : "f"(x));
    return r;
}
__device__ __forceinline__ void mma_f16_b2(float c[4], const uint32_t a[4],
                                           uint32_t b0, uint32_t b1) {
    asm volatile("mma.sync.aligned.m16n8k16.row.col.f32.f16.f16.f32 "
                 "{%0,%1,%2,%3}, {%4,%5,%6,%7}, {%8,%9}, {%0,%1,%2,%3};"
                 : "+f"(c[0]), "+f"(c[1]), "+f"(c[2]), "+f"(c[3])
                 : "r"(a[0]), "r"(a[1]), "r"(a[2]), "r"(a[3]), "r"(b0), "r"(b1));
}
__device__ __forceinline__ uint32_t smem_u32(const void* p) {
    uint32_t r;
    asm("{ .reg .u64 t; cvta.to.shared.u64 t, %1; cvt.u32.u64 %0, t; }" : "=r"(r) : "l"(p));
    return r;
}
#define LDMATRIX_X4(r0, r1, r2, r3, addr) \
    asm volatile("ldmatrix.sync.aligned.m8n8.x4.shared.b16 {%0,%1,%2,%3}, [%4];" \
                 : "=r"(r0), "=r"(r1), "=r"(r2), "=r"(r3) : "r"(addr))
#define LDMATRIX_X4_T(r0, r1, r2, r3, addr) \
    asm volatile("ldmatrix.sync.aligned.m8n8.x4.trans.shared.b16 {%0,%1,%2,%3}, [%4];" \
                 : "=r"(r0), "=r"(r1), "=r"(r2), "=r"(r3) : "r"(addr))

// Weight scale 2^6 (exact) to avoid fp16 subnormals; descale in epilogue.
#define WSCALE 64.0f
#define WDESC  0.015625f

// ==================================================================
// fp16 mma.sync GEMM core — R13 shape, A frags via ldmatrix.x4 (R15),
// B frags via ldmatrix.x4.trans (NEW): B smem is plain row-major
// [32 k][136 f16] (pad 8 f16 -> row addr 16k mod 128, conflict-free).
// CTA tile 256x128, K-chunk 32, 512 threads = 16 warps (4m x 4n),
// warp tile 64x32, LDG register prefetch + cvt-on-store, double buffer.
// ==================================================================
#define GBM 256
#define GBN 128
#define GBK 32
#define AS_U32 (256 * 20)   // 5120 words
#define BS_U32 (16 * 136)   // 2176 words (= 32 x 136 f16)
#define BP16 136            // B row pitch in f16
#define GEMM_SMEM_BYTES ((AS_U32 + BS_U32) * 2 * 4)  // 58368

template <int ROPE_MODE>
__device__ __forceinline__ void gemm_core(
    const float* __restrict__ A, const float* __restrict__ B,
    float* __restrict__ C, int N, int K, int m0, int n0,
    const int* __restrict__ pos, uint32_t* smu)
{
    uint32_t* As = smu;                 // 2 buffers
    uint32_t* Bs = smu + 2 * AS_U32;
    const uint32_t sA = smem_u32(As);
    const uint32_t sB = smem_u32(Bs);

    const int tid = threadIdx.x;
    const int wid = tid >> 5, lane = tid & 31;
    const int g = lane >> 2, q = lane & 3;
    const int warp_m = wid >> 2;           // 0..3 (64 rows)
    const int warp_n = wid & 3;            // 0..3 (32 cols)

    // ldmatrix per-lane addressing for A fragments (non-trans):
    const int lrow = lane & 15;
    const int lcol = (lane >> 4) * 4;
    uint32_t a_lm[4];
#pragma unroll
    for (int mt = 0; mt < 4; mt++)
        a_lm[mt] = sA + (uint32_t)(((warp_m * 64 + mt * 16 + lrow) * 20 + lcol) * 4);

    // ldmatrix per-lane addressing for B fragments (trans):
    // tile t = lane>>3: kh = t&1, ntp = t>>1; row = (lane&7) + kh*8, col = ntp*8
    const int brow_lm = (lane & 7) + ((lane >> 3) & 1) * 8;
    const int bcol_lm = (lane >> 4) * 8;
    const uint32_t b_lm = sB + (uint32_t)((brow_lm * BP16 + warp_n * 32 + bcol_lm) * 2);

    // loaders: A 256x32 (4 float4/thread), B rows 2bj,2bj+1 (2 float4/thread)
    const int arow = tid >> 3;             // 0..63
    const int acol4 = (tid & 7) * 4;
    const int aw0 = (tid & 7) * 2;         // word offset in A row
    const int bj = tid >> 5;               // 0..15
    const int bcol4 = (tid & 31) * 4;
    const float* Ag = A + (size_t)(m0 + arow) * K + acol4;
    const float* Bg = B + (size_t)(2 * bj) * N + n0 + bcol4;

    float acc[4][4][4];
#pragma unroll
    for (int mt = 0; mt < 4; mt++)
#pragma unroll
        for (int nt = 0; nt < 4; nt++)
#pragma unroll
            for (int e = 0; e < 4; e++) acc[mt][nt][e] = 0.0f;

    float4 pa[4], pb0, pb1;
#pragma unroll
    for (int it = 0; it < 4; it++)
        pa[it] = *(const float4*)(Ag + (size_t)it * 64 * K);
    pb0 = *(const float4*)(Bg);
    pb1 = *(const float4*)(Bg + N);

    uint16_t* Bs16 = (uint16_t*)Bs;
#pragma unroll
    for (int it = 0; it < 4; it++) {
        uint2 w;
        w.x = pack_h2(pa[it].x, pa[it].y);
        w.y = pack_h2(pa[it].z, pa[it].w);
        *(uint2*)&As[(arow + it * 64) * 20 + aw0] = w;
    }
    {
        uint2 w0, w1;
        w0.x = pack_h2(pb0.x * WSCALE, pb0.y * WSCALE);
        w0.y = pack_h2(pb0.z * WSCALE, pb0.w * WSCALE);
        w1.x = pack_h2(pb1.x * WSCALE, pb1.y * WSCALE);
        w1.y = pack_h2(pb1.z * WSCALE, pb1.w * WSCALE);
        *(uint2*)&Bs16[(2 * bj) * BP16 + bcol4] = w0;
        *(uint2*)&Bs16[(2 * bj + 1) * BP16 + bcol4] = w1;
    }
    __syncthreads();

    const int nCh = K / GBK;
    for (int c = 0; c < nCh; c++) {
        const int b = c & 1;
        const uint32_t aOff = (uint32_t)(b * AS_U32 * 4);
        const uint32_t bOff = (uint32_t)(b * BS_U32 * 4);

        if (c + 1 < nCh) {
            const int k0 = (c + 1) * GBK;
#pragma unroll
            for (int it = 0; it < 4; it++)
                pa[it] = *(const float4*)(Ag + k0 + (size_t)it * 64 * K);
            pb0 = *(const float4*)(Bg + (size_t)k0 * N);
            pb1 = *(const float4*)(Bg + (size_t)(k0 + 1) * N);
        }

#pragma unroll
        for (int kk = 0; kk < 2; kk++) {
            uint32_t af[4][4];
#pragma unroll
            for (int mt = 0; mt < 4; mt++)
                LDMATRIX_X4(af[mt][0], af[mt][1], af[mt][2], af[mt][3],
                            a_lm[mt] + aOff + (uint32_t)(kk * 8 * 4));
#pragma unroll
            for (int pair = 0; pair < 2; pair++) {
                uint32_t r0, r1, r2, r3;
                LDMATRIX_X4_T(r0, r1, r2, r3,
                              b_lm + bOff + (uint32_t)((kk * 16 * BP16 + pair * 16) * 2));
#pragma unroll
                for (int mt = 0; mt < 4; mt++) {
                    mma_f16_b2(acc[mt][2 * pair],     af[mt], r0, r1);
                    mma_f16_b2(acc[mt][2 * pair + 1], af[mt], r2, r3);
                }
            }
        }

        if (c + 1 < nCh) {
            uint32_t* aw = As + (1 - b) * AS_U32;
            uint16_t* bw = (uint16_t*)(Bs + (1 - b) * BS_U32);
#pragma unroll
            for (int it = 0; it < 4; it++) {
                uint2 w;
                w.x = pack_h2(pa[it].x, pa[it].y);
                w.y = pack_h2(pa[it].z, pa[it].w);
                *(uint2*)&aw[(arow + it * 64) * 20 + aw0] = w;
            }
            uint2 w0, w1;
            w0.x = pack_h2(pb0.x * WSCALE, pb0.y * WSCALE);
            w0.y = pack_h2(pb0.z * WSCALE, pb0.w * WSCALE);
            w1.x = pack_h2(pb1.x * WSCALE, pb1.y * WSCALE);
            w1.y = pack_h2(pb1.z * WSCALE, pb1.w * WSCALE);
            *(uint2*)&bw[(2 * bj) * BP16 + bcol4] = w0;
            *(uint2*)&bw[(2 * bj + 1) * BP16 + bcol4] = w1;
        }
        __syncthreads();
    }

    // epilogue: descale weights (2^-6) + optional RoPE; thread owns pairs
    // (col, col+1) at rows (row, row+8)
#pragma unroll
    for (int mt = 0; mt < 4; mt++) {
        const int row = m0 + warp_m * 64 + mt * 16 + g;
        float p0 = 0.0f, p1 = 0.0f;
        if (ROPE_MODE) {
            p0 = (float)pos[row];
            p1 = (float)pos[row + 8];
        }
#pragma unroll
        for (int nt = 0; nt < 4; nt++) {
            const int col = n0 + warp_n * 32 + nt * 8 + q * 2;
            float v00 = acc[mt][nt][0] * WDESC, v01 = acc[mt][nt][1] * WDESC;
            float v10 = acc[mt][nt][2] * WDESC, v11 = acc[mt][nt][3] * WDESC;
            if (ROPE_MODE) {
                const int i = (col & 63) >> 1;   // RoPE pair index within head
                const float f = c_invfreq[i];
                float s0, c0, s1, c1;
                sincosf(p0 * f, &s0, &c0);
                sincosf(p1 * f, &s1, &c1);
                float o00 = fmaf(v00, c0, -v01 * s0);
                float o01 = fmaf(v00, s0,  v01 * c0);
                float o10 = fmaf(v10, c1, -v11 * s1);
                float o11 = fmaf(v10, s1,  v11 * c1);
                v00 = o00; v01 = o01; v10 = o10; v11 = o11;
            }
            *(float2*)(C + (size_t)row * N + col)       = make_float2(v00, v01);
            *(float2*)(C + (size_t)(row + 8) * N + col) = make_float2(v10, v11);
        }
    }
}

// Plain GEMM (O projection)
__global__ __launch_bounds__(512, 1)
void mma_gemm(const float* __restrict__ A, const float* __restrict__ B,
              float* __restrict__ C, int N, int K)
{
    extern __shared__ uint32_t smu[];
    gemm_core<0>(A, B, C, N, K, blockIdx.y * GBM, blockIdx.x * GBN, nullptr, smu);
}

// Fused QKV projection + RoPE.
// grid.x in [0,24): 0-15 -> Q (Wq, rope), 16-19 -> K (Wk, rope), 20-23 -> V (Wv).
__global__ __launch_bounds__(512, 1)
void mma_gemm_qkv(const float* __restrict__ X,
                  const float* __restrict__ Wq, const float* __restrict__ Wk,
                  const float* __restrict__ Wv,
                  float* __restrict__ Cq, float* __restrict__ Ck, float* __restrict__ Cv,
                  const int* __restrict__ pos)
{
    extern __shared__ uint32_t smu[];
    const int bx = blockIdx.x;
    const int m0 = blockIdx.y * GBM;
    if (bx < 16) {
        gemm_core<1>(X, Wq, Cq, DM, DM, m0, bx * GBN, pos, smu);
    } else if (bx < 20) {
        gemm_core<1>(X, Wk, Ck, KVD, DM, m0, (bx - 16) * GBN, pos, smu);
    } else {
        gemm_core<0>(X, Wv, Cv, KVD, DM, m0, (bx - 20) * GBN, nullptr, smu);
    }
}

// ==================================================================
// fp16 tensor-core flash attention (R15 config) with V fragments via
// ldmatrix.x4.trans (bv issues 64 -> 16 per warp/tile). V smem now
// plain row-major [64][72] f16 like K (pitch 144B conflict-free).
// ==================================================================
#define FA_K_PAD 36         // words (72 f16)
#define FA_V_P16 72         // V row pitch in f16
#define FA3_SMEM_U32 (64 * FA_K_PAD + 64 * 36 + 64)
#define FA3_SMEM_BYTES (FA3_SMEM_U32 * 4)   // 18688

// 0.125 * log2(e)
#define QSCALE 0.180336880111120429f

__global__ __launch_bounds__(256, 2)
void fa_mma_kernel(const float* __restrict__ Q, const float* __restrict__ K,
                   const float* __restrict__ V, const int* __restrict__ mask,
                   float* __restrict__ Oout)
{
    extern __shared__ uint32_t su[];
    uint32_t* Ksp = su;                       // [64][36] words
    uint32_t* Vsp = Ksp + 64 * FA_K_PAD;      // [64][36] words (plain layout)
    float*    kb  = (float*)(Vsp + 64 * 36);
    const uint32_t sK = smem_u32(Ksp);
    const uint32_t sV = smem_u32(Vsp);

    const int tid = threadIdx.x;
    const int wid = tid >> 5, lane = tid & 31;
    const int g = lane >> 2, q = lane & 3;
    // LPT: longest CTAs (highest qt) launch first
    const int qt = (gridDim.x - 1) - blockIdx.x;
    const int h = blockIdx.y, b = blockIdx.z;
    const int q0 = qt * 128;
    const int kvh = h >> 2;
    const int row0 = q0 + wid * 16 + g;

    // ldmatrix lane addressing for K fragments (non-trans, as R15)
    const int krowsel = (lane & 7) + ((lane >> 4) * 8);
    const int kcoladd = ((lane >> 3) & 1) * 4;
    const uint32_t k_lm = sK + (uint32_t)((krowsel * FA_K_PAD + kcoladd) * 4);

    // ldmatrix lane addressing for V fragments (trans):
    // tile t = lane>>3: kh = t&1, ntp = t>>1; row = (lane&7)+kh*8, col = ntp*8
    const int vrow_lm = (lane & 7) + ((lane >> 3) & 1) * 8;
    const int vcol_lm = (lane >> 4) * 8;
    const uint32_t v_lm = sV + (uint32_t)((vrow_lm * FA_V_P16 + vcol_lm) * 2);

    // Q fragments (fp16, prescaled by 0.125*log2e)
    uint32_t qa[4][4];
    {
        const float* Qr0 = Q + ((size_t)(b * SEQ) + row0) * DM + h * HD;
        const float* Qr1 = Qr0 + (size_t)8 * DM;
#pragma unroll
        for (int k4 = 0; k4 < 4; k4++) {
            const int k0 = k4 * 16 + 2 * q;
            float2 x0 = *(const float2*)(Qr0 + k0);
            float2 x1 = *(const float2*)(Qr1 + k0);
            float2 x2 = *(const float2*)(Qr0 + k0 + 8);
            float2 x3 = *(const float2*)(Qr1 + k0 + 8);
            qa[k4][0] = pack_h2(x0.x * QSCALE, x0.y * QSCALE);
            qa[k4][1] = pack_h2(x1.x * QSCALE, x1.y * QSCALE);
            qa[k4][2] = pack_h2(x2.x * QSCALE, x2.y * QSCALE);
            qa[k4][3] = pack_h2(x3.x * QSCALE, x3.y * QSCALE);
        }
    }

    float m0r = -1e30f, m1r = -1e30f;
    float l0r = 0.0f,  l1r = 0.0f;
    float oc[8][4];
#pragma unroll
    for (int nt = 0; nt < 8; nt++)
#pragma unroll
        for (int e = 0; e < 4; e++) oc[nt][e] = 0.0f;

    const int ktmax = 2 * qt + 1;
    for (int kt = 0; kt <= ktmax; kt++) {
        const int k0 = kt * 64;
        __syncthreads();

        // K and V tiles: 64x64 fp32 -> [64][36] words each (plain layout)
#pragma unroll
        for (int it = 0; it < 4; it++) {
            int idx = tid + it * 256;
            int r = idx >> 4, c4 = (idx & 15) * 4;
            const size_t grow = ((size_t)(b * SEQ) + k0 + r) * KVD + kvh * HD + c4;
            float4 kk = *(const float4*)(K + grow);
            uint2 wk;
            wk.x = pack_h2(kk.x, kk.y);
            wk.y = pack_h2(kk.z, kk.w);
            *(uint2*)&Ksp[r * 36 + (c4 >> 1)] = wk;
            float4 vv = *(const float4*)(V + grow);
            uint2 wv;
            wv.x = pack_h2(vv.x, vv.y);
            wv.y = pack_h2(vv.z, vv.w);
            *(uint2*)&Vsp[r * 36 + (c4 >> 1)] = wv;
        }
        if (tid < 64)
            kb[tid] = (mask[b * SEQ + k0 + tid] > 0) ? 0.0f : -1e30f;
        __syncthreads();

        // S = (Q*qscale) @ K^T   (4 ksteps of K=16; K frags via ldmatrix)
        float sc[8][4];
#pragma unroll
        for (int nt = 0; nt < 8; nt++)
#pragma unroll
            for (int e = 0; e < 4; e++) sc[nt][e] = 0.0f;

#pragma unroll
        for (int k4 = 0; k4 < 4; k4++) {
#pragma unroll
            for (int p = 0; p < 4; p++) {
                uint32_t r0, r1, r2, r3;
                LDMATRIX_X4(r0, r1, r2, r3,
                            k_lm + (uint32_t)(((p * 16) * FA_K_PAD + k4 * 8) * 4));
                mma_f16_b2(sc[2 * p],     qa[k4], r0, r1);
                mma_f16_b2(sc[2 * p + 1], qa[k4], r2, r3);
            }
        }

        // causal + mask bias
#pragma unroll
        for (int nt = 0; nt < 8; nt++) {
            const int c0 = k0 + nt * 8 + 2 * q;
            const float kb0 = kb[nt * 8 + 2 * q];
            const float kb1 = kb[nt * 8 + 2 * q + 1];
            sc[nt][0] = (c0     <= row0    ) ? sc[nt][0] + kb0 : -1e30f;
            sc[nt][1] = (c0 + 1 <= row0    ) ? sc[nt][1] + kb1 : -1e30f;
            sc[nt][2] = (c0     <= row0 + 8) ? sc[nt][2] + kb0 : -1e30f;
            sc[nt][3] = (c0 + 1 <= row0 + 8) ? sc[nt][3] + kb1 : -1e30f;
        }

        float mx0 = -1e30f, mx1 = -1e30f;
#pragma unroll
        for (int nt = 0; nt < 8; nt++) {
            mx0 = fmaxf(mx0, fmaxf(sc[nt][0], sc[nt][1]));
            mx1 = fmaxf(mx1, fmaxf(sc[nt][2], sc[nt][3]));
        }
        mx0 = fmaxf(mx0, __shfl_xor_sync(0xffffffffu, mx0, 1));
        mx0 = fmaxf(mx0, __shfl_xor_sync(0xffffffffu, mx0, 2));
        mx1 = fmaxf(mx1, __shfl_xor_sync(0xffffffffu, mx1, 1));
        mx1 = fmaxf(mx1, __shfl_xor_sync(0xffffffffu, mx1, 2));

        const float mn0 = fmaxf(m0r, mx0);
        const float mn1 = fmaxf(m1r, mx1);
        const float al0 = ex2f(m0r - mn0);   // base-2 domain
        const float al1 = ex2f(m1r - mn1);
        m0r = mn0; m1r = mn1;

        // P = exp2(S - m), packed straight into fp16 A-fragments (registers)
        uint32_t pf[4][4];
        float s0 = 0.0f, s1 = 0.0f;
#pragma unroll
        for (int nt = 0; nt < 8; nt++) {
            float p0 = ex2f(sc[nt][0] - mn0);
            float p1 = ex2f(sc[nt][1] - mn0);
            float p2 = ex2f(sc[nt][2] - mn1);
            float p3 = ex2f(sc[nt][3] - mn1);
            s0 += p0 + p1; s1 += p2 + p3;
            const int k4 = nt >> 1;
            if (nt & 1) {
                pf[k4][2] = pack_h2(p0, p1);
                pf[k4][3] = pack_h2(p2, p3);
            } else {
                pf[k4][0] = pack_h2(p0, p1);
                pf[k4][1] = pack_h2(p2, p3);
            }
        }
        s0 += __shfl_xor_sync(0xffffffffu, s0, 1);
        s0 += __shfl_xor_sync(0xffffffffu, s0, 2);
        s1 += __shfl_xor_sync(0xffffffffu, s1, 1);
        s1 += __shfl_xor_sync(0xffffffffu, s1, 2);
        l0r = al0 * l0r + s0;
        l1r = al1 * l1r + s1;

#pragma unroll
        for (int nt = 0; nt < 8; nt++) {
            oc[nt][0] *= al0; oc[nt][1] *= al0;
            oc[nt][2] *= al1; oc[nt][3] *= al1;
        }

        // O += P @ V  (4 ksteps of K=16; A in registers, V via ldmatrix.trans)
#pragma unroll
        for (int k4 = 0; k4 < 4; k4++) {
#pragma unroll
            for (int ns = 0; ns < 4; ns++) {
                uint32_t r0, r1, r2, r3;
                LDMATRIX_X4_T(r0, r1, r2, r3,
                              v_lm + (uint32_t)(((k4 * 16) * FA_V_P16 + ns * 16) * 2));
                mma_f16_b2(oc[2 * ns],     pf[k4], r0, r1);
                mma_f16_b2(oc[2 * ns + 1], pf[k4], r2, r3);
            }
        }
    }

    const float inv0 = 1.0f / l0r;
    const float inv1 = 1.0f / l1r;
    float* O0 = Oout + ((size_t)(b * SEQ) + row0) * DM + h * HD;
    float* O1 = O0 + (size_t)8 * DM;
#pragma unroll
    for (int nt = 0; nt < 8; nt++) {
        const int col = nt * 8 + 2 * q;
        *(float2*)(O0 + col) = make_float2(oc[nt][0] * inv0, oc[nt][1] * inv0);
        *(float2*)(O1 + col) = make_float2(oc[nt][2] * inv1, oc[nt][3] * inv1);
    }
}

// ------------------------------------------------------------------
// Launch
// ------------------------------------------------------------------
extern "C" void kernel_launch(void* const* d_in, const int* in_sizes, int n_in,
                              void* d_out, int out_size)
{
    (void)in_sizes; (void)n_in; (void)out_size;
    const float* X    = (const float*)d_in[0];
    const int*   mask = (const int*)  d_in[1];
    const int*   pos  = (const int*)  d_in[2];
    const float* Wq   = (const float*)d_in[3];
    const float* Wk   = (const float*)d_in[4];
    const float* Wv   = (const float*)d_in[5];
    const float* Wo   = (const float*)d_in[6];
    float* out = (float*)d_out;

    float *q, *k, *v, *attn;
    cudaGetSymbolAddress((void**)&q,    g_q);
    cudaGetSymbolAddress((void**)&k,    g_k);
    cudaGetSymbolAddress((void**)&v,    g_v);
    cudaGetSymbolAddress((void**)&attn, g_attn);

    cudaFuncSetAttribute(mma_gemm, cudaFuncAttributeMaxDynamicSharedMemorySize, GEMM_SMEM_BYTES);
    cudaFuncSetAttribute(mma_gemm_qkv, cudaFuncAttributeMaxDynamicSharedMemorySize, GEMM_SMEM_BYTES);
    cudaFuncSetAttribute(fa_mma_kernel, cudaFuncAttributeMaxDynamicSharedMemorySize, FA3_SMEM_BYTES);

    // Fused QKV projections + RoPE (24 column tiles: 16 Q, 4 K, 4 V)
    mma_gemm_qkv<<<dim3(24, TOK / GBM), 512, GEMM_SMEM_BYTES>>>(X, Wq, Wk, Wv, q, k, v, pos);

    // fp16 tensor-core flash attention (full ldmatrix frags, P in registers)
    fa_mma_kernel<<<dim3(SEQ / 128, NH, BATCH), 256, FA3_SMEM_BYTES>>>(q, k, v, mask, attn);

    // Output projection
    mma_gemm<<<dim3(DM / GBN, TOK / GBM), 512, GEMM_SMEM_BYTES>>>(attn, Wo, out, DM, DM);
}

// round 17
// speedup vs baseline: 1.3675x; 1.0553x over previous
#include <cuda_runtime.h>
#include <cuda_fp16.h>
#include <cstdint>
#include <cstddef>

// Problem constants
#define SEQ   2048
#define BATCH 2
#define TOK   (SEQ * BATCH)   // 4096
#define DM    2048
#define NH    32
#define NKV   8
#define HD    64
#define KVD   (NKV * HD)      // 512

// ------------------------------------------------------------------
// Scratch (device globals; no cudaMalloc allowed) — fp16 everywhere
// ------------------------------------------------------------------
__device__ __half g_xh[(size_t)TOK * DM];
__device__ __half g_wqh[(size_t)DM * DM];
__device__ __half g_wkh[(size_t)DM * KVD];
__device__ __half g_wvh[(size_t)DM * KVD];
__device__ __half g_woh[(size_t)DM * DM];
__device__ __half g_qh[(size_t)TOK * DM];
__device__ __half g_kh[(size_t)TOK * KVD];
__device__ __half g_vh[(size_t)TOK * KVD];
__device__ __half g_ah[(size_t)TOK * DM];

// Exact fp32 rounding of 10000^(-i/32), i = 0..31
__device__ __constant__ float c_invfreq[32] = {
    1.0f, 0.7498942093324559f, 0.5623413251903491f, 0.4216965034285822f,
    0.31622776601683794f, 0.23713737056616552f, 0.17782794100389228f, 0.1333521432163324f,
    0.1f, 0.07498942093324559f, 0.05623413251903491f, 0.04216965034285822f,
    0.031622776601683794f, 0.023713737056616552f, 0.017782794100389228f, 0.01333521432163324f,
    0.01f, 0.007498942093324559f, 0.005623413251903491f, 0.004216965034285822f,
    0.0031622776601683794f, 0.0023713737056616552f, 0.0017782794100389228f, 0.001333521432163324f,
    0.001f, 0.0007498942093324559f, 0.0005623413251903491f, 0.0004216965034285822f,
    0.00031622776601683794f, 0.00023713737056616552f, 0.00017782794100389228f, 0.0001333521432163324f
};

// ------------------------------------------------------------------
// fp16 / cp.async helpers (baseline PTX, works on compute_103)
// ------------------------------------------------------------------
__device__ __forceinline__ uint32_t pack_h2(float lo, float hi) {
    __half2 h = __floats2half2_rn(lo, hi);
    return *reinterpret_cast<uint32_t*>(&h);
}
__device__ __forceinline__ float ex2f(float x) {
    float r;
    asm("ex2.approx.f32 %0, %1;" : "=f"(r) : "f"(x));
    return r;
}
__device__ __forceinline__ void mma_f16_b2(float c[4], const uint32_t a[4],
                                           uint32_t b0, uint32_t b1) {
    asm volatile("mma.sync.aligned.m16n8k16.row.col.f32.f16.f16.f32 "
                 "{%0,%1,%2,%3}, {%4,%5,%6,%7}, {%8,%9}, {%0,%1,%2,%3};"
                 : "+f"(c[0]), "+f"(c[1]), "+f"(c[2]), "+f"(c[3])
                 : "r"(a[0]), "r"(a[1]), "r"(a[2]), "r"(a[3]), "r"(b0), "r"(b1));
}
__device__ __forceinline__ uint32_t smem_u32(const void* p) {
    uint32_t r;
    asm("{ .reg .u64 t; cvta.to.shared.u64 t, %1; cvt.u32.u64 %0, t; }" : "=r"(r) : "l"(p));
    return r;
}
__device__ __forceinline__ void cp_async16(uint32_t dst, const void* src) {
    asm volatile("cp.async.ca.shared.global [%0], [%1], 16;" :: "r"(dst), "l"(src));
}
#define CP_COMMIT() asm volatile("cp.async.commit_group;" ::: "memory")
#define CP_WAIT0()  asm volatile("cp.async.wait_group 0;" ::: "memory")
#define LDMATRIX_X4(r0, r1, r2, r3, addr) \
    asm volatile("ldmatrix.sync.aligned.m8n8.x4.shared.b16 {%0,%1,%2,%3}, [%4];" \
                 : "=r"(r0), "=r"(r1), "=r"(r2), "=r"(r3) : "r"(addr))
#define LDMATRIX_X4_T(r0, r1, r2, r3, addr) \
    asm volatile("ldmatrix.sync.aligned.m8n8.x4.trans.shared.b16 {%0,%1,%2,%3}, [%4];" \
                 : "=r"(r0), "=r"(r1), "=r"(r2), "=r"(r3) : "r"(addr))

// Weight scale 2^6 (exact) to avoid fp16 subnormals; descale in epilogue.
#define WSCALE 64.0f
#define WDESC  0.015625f

// ==================================================================
// Pre-pass: fp32 -> fp16 (optionally scaled), 4 elems/thread
// ==================================================================
__global__ void cvt16(const float* __restrict__ in, __half* __restrict__ out,
                      float scale, int n4)
{
    int i = blockIdx.x * blockDim.x + threadIdx.x;
    if (i >= n4) return;
    float4 v = ((const float4*)in)[i];
    __half2* o = (__half2*)out + (size_t)i * 2;
    o[0] = __floats2half2_rn(v.x * scale, v.y * scale);
    o[1] = __floats2half2_rn(v.z * scale, v.w * scale);
}

// ==================================================================
// fp16 GEMM core — R16 fragment scheme (ldmatrix A + ldmatrix.trans B),
// loaders replaced by cp.async of fp16 data (zero cvt / zero STS).
// CTA tile 256x128, K-chunk 32, 512 threads = 16 warps (4m x 4n).
// A smem: [256][20] words (32 f16 data + pad). B smem: [32][136] f16.
// OUT_HALF=1 stores __half2 (qkv); 0 stores float2 (final out).
// ==================================================================
#define GBM 256
#define GBN 128
#define GBK 32
#define AS_U32 (256 * 20)   // 5120 words
#define BS_U32 (32 * 68)    // 2176 words (= 32 x 136 f16)
#define BP16 136            // B row pitch in f16
#define GEMM_SMEM_BYTES ((AS_U32 + BS_U32) * 2 * 4)  // 58368

template <int ROPE_MODE, int OUT_HALF>
__device__ __forceinline__ void gemm_core(
    const __half* __restrict__ A, const __half* __restrict__ B,
    void* __restrict__ Cout, int N, int K, int m0, int n0,
    const int* __restrict__ pos, uint32_t* smu)
{
    uint32_t* As = smu;                 // 2 buffers
    uint32_t* Bs = smu + 2 * AS_U32;
    const uint32_t sA = smem_u32(As);
    const uint32_t sB = smem_u32(Bs);

    const int tid = threadIdx.x;
    const int wid = tid >> 5, lane = tid & 31;
    const int g = lane >> 2, q = lane & 3;
    const int warp_m = wid >> 2;           // 0..3 (64 rows)
    const int warp_n = wid & 3;            // 0..3 (32 cols)

    // ldmatrix per-lane addressing for A fragments (non-trans):
    const int lrow = lane & 15;
    const int lcol = (lane >> 4) * 4;
    uint32_t a_lm[4];
#pragma unroll
    for (int mt = 0; mt < 4; mt++)
        a_lm[mt] = sA + (uint32_t)(((warp_m * 64 + mt * 16 + lrow) * 20 + lcol) * 4);

    // ldmatrix per-lane addressing for B fragments (trans):
    const int brow_lm = (lane & 7) + ((lane >> 3) & 1) * 8;
    const int bcol_lm = (lane >> 4) * 8;
    const uint32_t b_lm = sB + (uint32_t)((brow_lm * BP16 + warp_n * 32 + bcol_lm) * 2);

    // cp.async loader indices:
    // A: 2 segs/thread: rows arow0, arow0+128; 16B at (tid&3)*8 f16
    const int arow0 = tid >> 2;
    const int acol8 = (tid & 3) * 8;
    // B: 1 seg/thread: row tid>>4 (0..31), 16B at (tid&15)*8 f16
    const int brow = tid >> 4;
    const int bcol8 = (tid & 15) * 8;
    const __half* Ag0 = A + (size_t)(m0 + arow0) * K + acol8;
    const __half* Ag1 = Ag0 + (size_t)128 * K;
    const __half* Bg = B + (size_t)brow * N + n0 + bcol8;
    const uint32_t aDst0 = (uint32_t)((arow0 * 20 + (tid & 3) * 4) * 4);
    const uint32_t aDst1 = (uint32_t)(((arow0 + 128) * 20 + (tid & 3) * 4) * 4);
    const uint32_t bDst  = (uint32_t)((brow * 68 + (tid & 15) * 4) * 4);

    float acc[4][4][4];
#pragma unroll
    for (int mt = 0; mt < 4; mt++)
#pragma unroll
        for (int nt = 0; nt < 4; nt++)
#pragma unroll
            for (int e = 0; e < 4; e++) acc[mt][nt][e] = 0.0f;

    // prologue: issue chunk 0 into buffer 0
    cp_async16(sA + aDst0, Ag0);
    cp_async16(sA + aDst1, Ag1);
    cp_async16(sB + bDst, Bg);
    CP_COMMIT();

    const int nCh = K / GBK;
    for (int c = 0; c < nCh; c++) {
        const int b = c & 1;
        const uint32_t aOff = (uint32_t)(b * AS_U32 * 4);
        const uint32_t bOff = (uint32_t)(b * BS_U32 * 4);
        CP_WAIT0();
        __syncthreads();

        if (c + 1 < nCh) {
            const int k0 = (c + 1) * GBK;
            const uint32_t aO = (uint32_t)((1 - b) * AS_U32 * 4);
            const uint32_t bO = (uint32_t)((1 - b) * BS_U32 * 4);
            cp_async16(sA + aO + aDst0, Ag0 + k0);
            cp_async16(sA + aO + aDst1, Ag1 + k0);
            cp_async16(sB + bO + bDst, Bg + (size_t)k0 * N);
            CP_COMMIT();
        }

#pragma unroll
        for (int kk = 0; kk < 2; kk++) {
            uint32_t af[4][4];
#pragma unroll
            for (int mt = 0; mt < 4; mt++)
                LDMATRIX_X4(af[mt][0], af[mt][1], af[mt][2], af[mt][3],
                            a_lm[mt] + aOff + (uint32_t)(kk * 8 * 4));
#pragma unroll
            for (int pair = 0; pair < 2; pair++) {
                uint32_t r0, r1, r2, r3;
                LDMATRIX_X4_T(r0, r1, r2, r3,
                              b_lm + bOff + (uint32_t)((kk * 16 * BP16 + pair * 16) * 2));
#pragma unroll
                for (int mt = 0; mt < 4; mt++) {
                    mma_f16_b2(acc[mt][2 * pair],     af[mt], r0, r1);
                    mma_f16_b2(acc[mt][2 * pair + 1], af[mt], r2, r3);
                }
            }
        }
    }

    // epilogue: descale weights (2^-6) + optional RoPE
#pragma unroll
    for (int mt = 0; mt < 4; mt++) {
        const int row = m0 + warp_m * 64 + mt * 16 + g;
        float p0 = 0.0f, p1 = 0.0f;
        if (ROPE_MODE) {
            p0 = (float)pos[row];
            p1 = (float)pos[row + 8];
        }
#pragma unroll
        for (int nt = 0; nt < 4; nt++) {
            const int col = n0 + warp_n * 32 + nt * 8 + q * 2;
            float v00 = acc[mt][nt][0] * WDESC, v01 = acc[mt][nt][1] * WDESC;
            float v10 = acc[mt][nt][2] * WDESC, v11 = acc[mt][nt][3] * WDESC;
            if (ROPE_MODE) {
                const int i = (col & 63) >> 1;
                const float f = c_invfreq[i];
                float s0, c0, s1, c1;
                sincosf(p0 * f, &s0, &c0);
                sincosf(p1 * f, &s1, &c1);
                float o00 = fmaf(v00, c0, -v01 * s0);
                float o01 = fmaf(v00, s0,  v01 * c0);
                float o10 = fmaf(v10, c1, -v11 * s1);
                float o11 = fmaf(v10, s1,  v11 * c1);
                v00 = o00; v01 = o01; v10 = o10; v11 = o11;
            }
            if (OUT_HALF) {
                __half2* C0 = (__half2*)((__half*)Cout + (size_t)row * N + col);
                __half2* C1 = (__half2*)((__half*)Cout + (size_t)(row + 8) * N + col);
                *C0 = __floats2half2_rn(v00, v01);
                *C1 = __floats2half2_rn(v10, v11);
            } else {
                float* C = (float*)Cout;
                *(float2*)(C + (size_t)row * N + col)       = make_float2(v00, v01);
                *(float2*)(C + (size_t)(row + 8) * N + col) = make_float2(v10, v11);
            }
        }
    }
}

// Plain GEMM (O projection): A = attn fp16, B = Wo fp16 (scaled), out fp32
__global__ __launch_bounds__(512, 1)
void mma_gemm(const __half* __restrict__ A, const __half* __restrict__ B,
              float* __restrict__ C, int N, int K)
{
    extern __shared__ uint32_t smu[];
    gemm_core<0, 0>(A, B, C, N, K, blockIdx.y * GBM, blockIdx.x * GBN, nullptr, smu);
}

// Fused QKV projection + RoPE; fp16 in, fp16 out.
__global__ __launch_bounds__(512, 1)
void mma_gemm_qkv(const __half* __restrict__ X,
                  const __half* __restrict__ Wq, const __half* __restrict__ Wk,
                  const __half* __restrict__ Wv,
                  __half* __restrict__ Cq, __half* __restrict__ Ck, __half* __restrict__ Cv,
                  const int* __restrict__ pos)
{
    extern __shared__ uint32_t smu[];
    const int bx = blockIdx.x;
    const int m0 = blockIdx.y * GBM;
    if (bx < 16) {
        gemm_core<1, 1>(X, Wq, Cq, DM, DM, m0, bx * GBN, pos, smu);
    } else if (bx < 20) {
        gemm_core<1, 1>(X, Wk, Ck, KVD, DM, m0, (bx - 16) * GBN, pos, smu);
    } else {
        gemm_core<0, 1>(X, Wv, Cv, KVD, DM, m0, (bx - 20) * GBN, nullptr, smu);
    }
}

// ==================================================================
// fp16 flash attention — R16 fragment scheme, K/V via cp.async fp16
// double-buffered. Q/K/V/attn all fp16 in global.
// ==================================================================
#define FA_KV_U32 (64 * 36)    // one K or V buffer, words
#define FA_P16 72              // row pitch in f16
#define FA3_SMEM_U32 (4 * FA_KV_U32 + 64)
#define FA3_SMEM_BYTES (FA3_SMEM_U32 * 4)   // 37120

// 0.125 * log2(e)
#define QSCALE 0.180336880111120429f

__global__ __launch_bounds__(256, 2)
void fa_mma_kernel(const __half* __restrict__ Q, const __half* __restrict__ K,
                   const __half* __restrict__ V, const int* __restrict__ mask,
                   __half* __restrict__ Oout)
{
    extern __shared__ uint32_t su[];
    uint32_t* Ksp = su;                       // 2 x [64][36] words
    uint32_t* Vsp = Ksp + 2 * FA_KV_U32;      // 2 x [64][36] words
    float*    kb  = (float*)(Vsp + 2 * FA_KV_U32);
    const uint32_t sK = smem_u32(Ksp);
    const uint32_t sV = smem_u32(Vsp);

    const int tid = threadIdx.x;
    const int wid = tid >> 5, lane = tid & 31;
    const int g = lane >> 2, q = lane & 3;
    // LPT: longest CTAs (highest qt) launch first
    const int qt = (gridDim.x - 1) - blockIdx.x;
    const int h = blockIdx.y, b = blockIdx.z;
    const int q0 = qt * 128;
    const int kvh = h >> 2;
    const int row0 = q0 + wid * 16 + g;

    // ldmatrix lane addressing (as R16)
    const int krowsel = (lane & 7) + ((lane >> 4) * 8);
    const int kcoladd = ((lane >> 3) & 1) * 4;
    const uint32_t k_lm = sK + (uint32_t)((krowsel * 36 + kcoladd) * 4);
    const int vrow_lm = (lane & 7) + ((lane >> 3) & 1) * 8;
    const int vcol_lm = (lane >> 4) * 8;
    const uint32_t v_lm = sV + (uint32_t)((vrow_lm * FA_P16 + vcol_lm) * 2);

    // cp.async loader indices: segs tid and tid+256; row = s>>3, 16B at (s&7)*8 f16
    const int lr0 = tid >> 3;              // rows lr0 and lr0+32
    const int lc8 = (tid & 7) * 8;
    const size_t kvbase = (size_t)(b * SEQ) * KVD + kvh * HD + lc8;
    const uint32_t d0 = (uint32_t)((lr0 * 36 + (tid & 7) * 4) * 4);
    const uint32_t d1 = (uint32_t)(((lr0 + 32) * 36 + (tid & 7) * 4) * 4);

    // Q fragments (fp16 global, rescaled by 0.125*log2e in fp32)
    uint32_t qa[4][4];
    {
        const __half* Qr0 = Q + ((size_t)(b * SEQ) + row0) * DM + h * HD;
        const __half* Qr1 = Qr0 + (size_t)8 * DM;
#pragma unroll
        for (int k4 = 0; k4 < 4; k4++) {
            const int k0 = k4 * 16 + 2 * q;
            float2 x0 = __half22float2(*(const __half2*)(Qr0 + k0));
            float2 x1 = __half22float2(*(const __half2*)(Qr1 + k0));
            float2 x2 = __half22float2(*(const __half2*)(Qr0 + k0 + 8));
            float2 x3 = __half22float2(*(const __half2*)(Qr1 + k0 + 8));
            qa[k4][0] = pack_h2(x0.x * QSCALE, x0.y * QSCALE);
            qa[k4][1] = pack_h2(x1.x * QSCALE, x1.y * QSCALE);
            qa[k4][2] = pack_h2(x2.x * QSCALE, x2.y * QSCALE);
            qa[k4][3] = pack_h2(x3.x * QSCALE, x3.y * QSCALE);
        }
    }

    float m0r = -1e30f, m1r = -1e30f;
    float l0r = 0.0f,  l1r = 0.0f;
    float oc[8][4];
#pragma unroll
    for (int nt = 0; nt < 8; nt++)
#pragma unroll
        for (int e = 0; e < 4; e++) oc[nt][e] = 0.0f;

    const int ktmax = 2 * qt + 1;

    // prologue: issue K/V tile 0 into buffer 0
    {
        const __half* Kg = K + kvbase + (size_t)lr0 * KVD;
        const __half* Vg = V + kvbase + (size_t)lr0 * KVD;
        cp_async16(sK + d0, Kg);
        cp_async16(sK + d1, Kg + (size_t)32 * KVD);
        cp_async16(sV + d0, Vg);
        cp_async16(sV + d1, Vg + (size_t)32 * KVD);
        CP_COMMIT();
    }

    for (int kt = 0; kt <= ktmax; kt++) {
        const int k0 = kt * 64;
        const int bb = kt & 1;
        const uint32_t kOff = (uint32_t)(bb * FA_KV_U32 * 4);
        CP_WAIT0();
        __syncthreads();   // tile landed; prev compute done

        // issue next tile into the other buffer (overlaps compute)
        if (kt < ktmax) {
            const uint32_t o = (uint32_t)((1 - bb) * FA_KV_U32 * 4);
            const __half* Kg = K + kvbase + (size_t)(k0 + 64 + lr0) * KVD;
            const __half* Vg = V + kvbase + (size_t)(k0 + 64 + lr0) * KVD;
            cp_async16(sK + o + d0, Kg);
            cp_async16(sK + o + d1, Kg + (size_t)32 * KVD);
            cp_async16(sV + o + d0, Vg);
            cp_async16(sV + o + d1, Vg + (size_t)32 * KVD);
            CP_COMMIT();
        }
        if (tid < 64)
            kb[tid] = (mask[b * SEQ + k0 + tid] > 0) ? 0.0f : -1e30f;
        __syncthreads();   // kb visible

        // S = (Q*qscale) @ K^T
        float sc[8][4];
#pragma unroll
        for (int nt = 0; nt < 8; nt++)
#pragma unroll
            for (int e = 0; e < 4; e++) sc[nt][e] = 0.0f;

#pragma unroll
        for (int k4 = 0; k4 < 4; k4++) {
#pragma unroll
            for (int p = 0; p < 4; p++) {
                uint32_t r0, r1, r2, r3;
                LDMATRIX_X4(r0, r1, r2, r3,
                            k_lm + kOff + (uint32_t)(((p * 16) * 36 + k4 * 8) * 4));
                mma_f16_b2(sc[2 * p],     qa[k4], r0, r1);
                mma_f16_b2(sc[2 * p + 1], qa[k4], r2, r3);
            }
        }

        // causal + mask bias
#pragma unroll
        for (int nt = 0; nt < 8; nt++) {
            const int c0 = k0 + nt * 8 + 2 * q;
            const float kb0 = kb[nt * 8 + 2 * q];
            const float kb1 = kb[nt * 8 + 2 * q + 1];
            sc[nt][0] = (c0     <= row0    ) ? sc[nt][0] + kb0 : -1e30f;
            sc[nt][1] = (c0 + 1 <= row0    ) ? sc[nt][1] + kb1 : -1e30f;
            sc[nt][2] = (c0     <= row0 + 8) ? sc[nt][2] + kb0 : -1e30f;
            sc[nt][3] = (c0 + 1 <= row0 + 8) ? sc[nt][3] + kb1 : -1e30f;
        }

        float mx0 = -1e30f, mx1 = -1e30f;
#pragma unroll
        for (int nt = 0; nt < 8; nt++) {
            mx0 = fmaxf(mx0, fmaxf(sc[nt][0], sc[nt][1]));
            mx1 = fmaxf(mx1, fmaxf(sc[nt][2], sc[nt][3]));
        }
        mx0 = fmaxf(mx0, __shfl_xor_sync(0xffffffffu, mx0, 1));
        mx0 = fmaxf(mx0, __shfl_xor_sync(0xffffffffu, mx0, 2));
        mx1 = fmaxf(mx1, __shfl_xor_sync(0xffffffffu, mx1, 1));
        mx1 = fmaxf(mx1, __shfl_xor_sync(0xffffffffu, mx1, 2));

        const float mn0 = fmaxf(m0r, mx0);
        const float mn1 = fmaxf(m1r, mx1);
        const float al0 = ex2f(m0r - mn0);
        const float al1 = ex2f(m1r - mn1);
        m0r = mn0; m1r = mn1;

        // P = exp2(S - m), packed into fp16 A-fragments (registers)
        uint32_t pf[4][4];
        float s0 = 0.0f, s1 = 0.0f;
#pragma unroll
        for (int nt = 0; nt < 8; nt++) {
            float p0 = ex2f(sc[nt][0] - mn0);
            float p1 = ex2f(sc[nt][1] - mn0);
            float p2 = ex2f(sc[nt][2] - mn1);
            float p3 = ex2f(sc[nt][3] - mn1);
            s0 += p0 + p1; s1 += p2 + p3;
            const int k4 = nt >> 1;
            if (nt & 1) {
                pf[k4][2] = pack_h2(p0, p1);
                pf[k4][3] = pack_h2(p2, p3);
            } else {
                pf[k4][0] = pack_h2(p0, p1);
                pf[k4][1] = pack_h2(p2, p3);
            }
        }
        s0 += __shfl_xor_sync(0xffffffffu, s0, 1);
        s0 += __shfl_xor_sync(0xffffffffu, s0, 2);
        s1 += __shfl_xor_sync(0xffffffffu, s1, 1);
        s1 += __shfl_xor_sync(0xffffffffu, s1, 2);
        l0r = al0 * l0r + s0;
        l1r = al1 * l1r + s1;

#pragma unroll
        for (int nt = 0; nt < 8; nt++) {
            oc[nt][0] *= al0; oc[nt][1] *= al0;
            oc[nt][2] *= al1; oc[nt][3] *= al1;
        }

        // O += P @ V  (V via ldmatrix.trans)
#pragma unroll
        for (int k4 = 0; k4 < 4; k4++) {
#pragma unroll
            for (int ns = 0; ns < 4; ns++) {
                uint32_t r0, r1, r2, r3;
                LDMATRIX_X4_T(r0, r1, r2, r3,
                              v_lm + kOff + (uint32_t)(((k4 * 16) * FA_P16 + ns * 16) * 2));
                mma_f16_b2(oc[2 * ns],     pf[k4], r0, r1);
                mma_f16_b2(oc[2 * ns + 1], pf[k4], r2, r3);
            }
        }
    }

    const float inv0 = 1.0f / l0r;
    const float inv1 = 1.0f / l1r;
    __half* O0 = Oout + ((size_t)(b * SEQ) + row0) * DM + h * HD;
    __half* O1 = O0 + (size_t)8 * DM;
#pragma unroll
    for (int nt = 0; nt < 8; nt++) {
        const int col = nt * 8 + 2 * q;
        *(__half2*)(O0 + col) = __floats2half2_rn(oc[nt][0] * inv0, oc[nt][1] * inv0);
        *(__half2*)(O1 + col) = __floats2half2_rn(oc[nt][2] * inv1, oc[nt][3] * inv1);
    }
}

// ------------------------------------------------------------------
// Launch
// ------------------------------------------------------------------
extern "C" void kernel_launch(void* const* d_in, const int* in_sizes, int n_in,
                              void* d_out, int out_size)
{
    (void)in_sizes; (void)n_in; (void)out_size;
    const float* X    = (const float*)d_in[0];
    const int*   mask = (const int*)  d_in[1];
    const int*   pos  = (const int*)  d_in[2];
    const float* Wq   = (const float*)d_in[3];
    const float* Wk   = (const float*)d_in[4];
    const float* Wv   = (const float*)d_in[5];
    const float* Wo   = (const float*)d_in[6];
    float* out = (float*)d_out;

    __half *xh, *wqh, *wkh, *wvh, *woh, *qh, *kh, *vh, *ah;
    cudaGetSymbolAddress((void**)&xh,  g_xh);
    cudaGetSymbolAddress((void**)&wqh, g_wqh);
    cudaGetSymbolAddress((void**)&wkh, g_wkh);
    cudaGetSymbolAddress((void**)&wvh, g_wvh);
    cudaGetSymbolAddress((void**)&woh, g_woh);
    cudaGetSymbolAddress((void**)&qh,  g_qh);
    cudaGetSymbolAddress((void**)&kh,  g_kh);
    cudaGetSymbolAddress((void**)&vh,  g_vh);
    cudaGetSymbolAddress((void**)&ah,  g_ah);

    cudaFuncSetAttribute(mma_gemm, cudaFuncAttributeMaxDynamicSharedMemorySize, GEMM_SMEM_BYTES);
    cudaFuncSetAttribute(mma_gemm_qkv, cudaFuncAttributeMaxDynamicSharedMemorySize, GEMM_SMEM_BYTES);
    cudaFuncSetAttribute(fa_mma_kernel, cudaFuncAttributeMaxDynamicSharedMemorySize, FA3_SMEM_BYTES);

    // Pre-passes: fp32 -> fp16 (weights scaled by 2^6)
    cvt16<<<(TOK * DM / 4) / 256, 256>>>(X, xh, 1.0f, TOK * DM / 4);
    cvt16<<<(DM * DM / 4) / 256, 256>>>(Wq, wqh, WSCALE, DM * DM / 4);
    cvt16<<<(DM * KVD / 4) / 256, 256>>>(Wk, wkh, WSCALE, DM * KVD / 4);
    cvt16<<<(DM * KVD / 4) / 256, 256>>>(Wv, wvh, WSCALE, DM * KVD / 4);
    cvt16<<<(DM * DM / 4) / 256, 256>>>(Wo, woh, WSCALE, DM * DM / 4);

    // Fused QKV projections + RoPE (fp16 out)
    mma_gemm_qkv<<<dim3(24, TOK / GBM), 512, GEMM_SMEM_BYTES>>>(xh, wqh, wkh, wvh,
                                                                qh, kh, vh, pos);

    // fp16 flash attention (cp.async double-buffered K/V)
    fa_mma_kernel<<<dim3(SEQ / 128, NH, BATCH), 256, FA3_SMEM_BYTES>>>(qh, kh, vh, mask, ah);

    // Output projection (fp32 out)
    mma_gemm<<<dim3(DM / GBN, TOK / GBM), 512, GEMM_SMEM_BYTES>>>(ah, woh, out, DM, DM);
}